// round 2
// baseline (speedup 1.0000x reference)
#include <cuda_runtime.h>
#include <math.h>

namespace {
constexpr int L   = 1024;
constexpr int D   = 1024;
constexpr int H   = 16;
constexpr int KVH = 8;
constexpr int HD  = 64;
constexpr int NS  = 128;
constexpr int DT  = 64;
constexpr int E   = 8;
constexpr int HID = 4096;
constexpr int PRJ = DT + 2*NS; // 320
constexpr int BM = 128, BN = 128, BK = 8, TM = 8, TN = 8;
}

// ------------------ scratch: device globals (allocation-free) ------------------
__device__ float g_xn[L*D];
__device__ float g_sn[L*D];
__device__ float g_snsel[L*D];
__device__ float g_proj[L*PRJ];
__device__ float g_delta[L*D];
__device__ float g_tmpssm[L*D];
__device__ float g_outssm[L*D];
__device__ float g_qlin[L*D];
__device__ float g_klin[L*KVH*HD];
__device__ float g_vlin[L*KVH*HD];
__device__ float g_qr[H*L*HD];
__device__ float g_kr[H*L*HD];
__device__ float g_vt[H*HD*L];
__device__ float g_scores[H*L*L];
__device__ float g_attnout[L*D];
__device__ float g_outattn[L*D];
__device__ float g_convsilu[L*D];
__device__ float g_outconv[L*D];
__device__ float g_weights[L*4];
__device__ float g_x2[L*D];
__device__ float g_vals[L*2];
__device__ int   g_topidx[L*2];
__device__ float g_w0[L];
__device__ float g_w1[L];
__device__ int   g_cnt[E];
__device__ int   g_tok[E*L];
__device__ int   g_slot[E*L];
__device__ float g_h1[L*2*HID];
__device__ float g_hh[L*HID];
__device__ float g_y[L*D];
__device__ float g_moe[2*L*D];

__device__ __forceinline__ float warpSum(float v){
    #pragma unroll
    for (int o = 16; o; o >>= 1) v += __shfl_xor_sync(0xffffffffu, v, o);
    return v;
}

// ------------------ generic NT GEMM: C[m,n] = sum_k A[m,k]*B[n,k] ------------------
// EPI: 0 none | 1 +x0[n] | 2 softplus(acc+x0[n]) | 3 x1[m*ldc+n]*sigmoid((acc+x0[n])*x2p[n])
//      | 5 MoE scatter: g_moe[(slot*L+tok)*D+n] = w_slot[tok]*(acc + x0[n])
// If eidx >= 0: M = g_cnt[eidx]; if GATHER: A row = g_tok[eidx*L + row].
template<int EPI, bool GATHER>
__global__ void __launch_bounds__(256)
gemm_nt(const float* __restrict__ A, const float* __restrict__ B, float* __restrict__ Cp,
        int M, int N, int K, int lda, int ldb, int ldc,
        long long sA, long long sB, long long sC,
        const float* __restrict__ x0, const float* __restrict__ x1,
        const float* __restrict__ x2p, int eidx)
{
    __shared__ float As[BK][BM];
    __shared__ float Bs[BK][BN];
    int bm = blockIdx.y, bn = blockIdx.x, bz = blockIdx.z;
    if (eidx >= 0) M = g_cnt[eidx];
    if (bm*BM >= M) return;
    A += bz*sA; B += bz*sB; Cp += bz*sC;
    int tid = threadIdx.x;
    int ar = tid >> 1, ac = (tid & 1)*4;
    int tx = tid & 15, ty = tid >> 4;
    int row0 = bm*BM;
    int arow = row0 + ar;
    bool aval = arow < M;
    int asrc = 0;
    if (aval) asrc = GATHER ? g_tok[eidx*L + arow] : arow;
    int brow = bn*BN + ar;
    bool bval = brow < N;
    float acc[TM][TN] = {};
    for (int k0 = 0; k0 < K; k0 += BK){
        float4 av = make_float4(0,0,0,0), bv = make_float4(0,0,0,0);
        if (aval) av = *(const float4*)&A[(long long)asrc*lda + k0 + ac];
        if (bval) bv = *(const float4*)&B[(long long)brow*ldb + k0 + ac];
        As[ac+0][ar]=av.x; As[ac+1][ar]=av.y; As[ac+2][ar]=av.z; As[ac+3][ar]=av.w;
        Bs[ac+0][ar]=bv.x; Bs[ac+1][ar]=bv.y; Bs[ac+2][ar]=bv.z; Bs[ac+3][ar]=bv.w;
        __syncthreads();
        #pragma unroll
        for (int k = 0; k < BK; k++){
            float a[TM], b[TN];
            *(float4*)&a[0] = *(const float4*)&As[k][ty*TM];
            *(float4*)&a[4] = *(const float4*)&As[k][ty*TM+4];
            *(float4*)&b[0] = *(const float4*)&Bs[k][tx*TN];
            *(float4*)&b[4] = *(const float4*)&Bs[k][tx*TN+4];
            #pragma unroll
            for (int i = 0; i < TM; i++)
                #pragma unroll
                for (int j = 0; j < TN; j++) acc[i][j] += a[i]*b[j];
        }
        __syncthreads();
    }
    #pragma unroll
    for (int i = 0; i < TM; i++){
        int m = row0 + ty*TM + i;
        if (m >= M) continue;
        #pragma unroll
        for (int j = 0; j < TN; j++){
            int n = bn*BN + tx*TN + j;
            if (n >= N) continue;
            float v = acc[i][j];
            if (EPI == 0){
                Cp[(long long)m*ldc + n] = v;
            } else if (EPI == 1){
                Cp[(long long)m*ldc + n] = v + x0[n];
            } else if (EPI == 2){
                float z = v + x0[n];
                Cp[(long long)m*ldc + n] = fmaxf(z, 0.f) + log1pf(__expf(-fabsf(z)));
            } else if (EPI == 3){
                float z = (v + x0[n]) * x2p[n];
                Cp[(long long)m*ldc + n] = x1[(long long)m*ldc + n] / (1.f + __expf(-z));
            } else if (EPI == 5){
                int tok = g_tok[eidx*L + m];
                int sl  = g_slot[eidx*L + m];
                float w = sl ? g_w1[tok] : g_w0[tok];
                g_moe[((long long)sl*L + tok)*D + n] = w * (v + x0[n]);
            }
        }
    }
}

// ------------------ elementwise / reduction kernels ------------------
__global__ void rms_kernel(const float* __restrict__ in, const float* __restrict__ w,
                           float* __restrict__ out){
    int t = blockIdx.x;
    const float* row = in + (long long)t*D;
    __shared__ float sred[8];
    __shared__ float sscale;
    float ss = 0.f;
    for (int d = threadIdx.x; d < D; d += 256){ float v = row[d]; ss += v*v; }
    ss = warpSum(ss);
    if ((threadIdx.x & 31) == 0) sred[threadIdx.x >> 5] = ss;
    __syncthreads();
    if (threadIdx.x == 0){
        float s = 0.f;
        #pragma unroll
        for (int i = 0; i < 8; i++) s += sred[i];
        sscale = rsqrtf(s*(1.f/D) + 1e-6f);
    }
    __syncthreads();
    float sc = sscale;
    for (int d = threadIdx.x; d < D; d += 256)
        out[(long long)t*D + d] = row[d]*sc*w[d];
}

__global__ void router_kernel(const float* __restrict__ rw){
    int t = blockIdx.x;
    __shared__ float sm[8][4];
    float acc[4] = {0,0,0,0};
    for (int d = threadIdx.x; d < D; d += 256){
        float xv = g_xn[(long long)t*D + d];
        #pragma unroll
        for (int j = 0; j < 4; j++) acc[j] += xv*rw[j*D + d];
    }
    #pragma unroll
    for (int j = 0; j < 4; j++) acc[j] = warpSum(acc[j]);
    if ((threadIdx.x & 31) == 0){
        #pragma unroll
        for (int j = 0; j < 4; j++) sm[threadIdx.x >> 5][j] = acc[j];
    }
    __syncthreads();
    if (threadIdx.x == 0){
        float lg[4];
        #pragma unroll
        for (int j = 0; j < 4; j++){ float s = 0.f; for (int w2 = 0; w2 < 8; w2++) s += sm[w2][j]; lg[j] = s; }
        float mx = fmaxf(fmaxf(lg[0], lg[1]), fmaxf(lg[2], lg[3]));
        float sum = 0.f;
        #pragma unroll
        for (int j = 0; j < 4; j++){ lg[j] = __expf(lg[j] - mx); sum += lg[j]; }
        const float c[4] = {0.5f, 0.2f, 0.15f, 0.15f};
        float s2 = 0.f;
        #pragma unroll
        for (int j = 0; j < 4; j++){ lg[j] = lg[j]/sum*c[j]; s2 += lg[j]; }
        #pragma unroll
        for (int j = 0; j < 4; j++) g_weights[t*4 + j] = lg[j]/s2;
    }
}

__global__ void scan_kernel(const float* __restrict__ A_log, const float* __restrict__ Dp){
    int w = threadIdx.x >> 5, lane = threadIdx.x & 31;
    int d = blockIdx.x*4 + w;
    float A0[4], h[4] = {0,0,0,0};
    #pragma unroll
    for (int i = 0; i < 4; i++) A0[i] = -__expf(A_log[d*NS + lane + 32*i]);
    float Dpd = Dp[d];
    for (int t = 0; t < L; t++){
        float dt = g_delta[(long long)t*D + d];
        float xt = g_snsel[(long long)t*D + d];
        float dx = dt*xt;
        float acc = 0.f;
        #pragma unroll
        for (int i = 0; i < 4; i++){
            float b = g_proj[(long long)t*PRJ + DT + lane + 32*i];
            float c = g_proj[(long long)t*PRJ + DT + NS + lane + 32*i];
            h[i] = __expf(dt*A0[i])*h[i] + dx*b;
            acc += h[i]*c;
        }
        acc = warpSum(acc);
        if (lane == 0)
            g_tmpssm[(long long)t*D + d] = acc + g_xn[(long long)t*D + d]*Dpd;
    }
}

__global__ void qrope_kernel(const float* __restrict__ qn_w){
    int t = blockIdx.x;
    int h = threadIdx.x >> 5, l = threadIdx.x & 31;
    float a = g_qlin[(long long)t*D + h*HD + l];
    float b = g_qlin[(long long)t*D + h*HD + l + 32];
    float ss = warpSum(a*a + b*b);
    float sc = rsqrtf(ss*(1.f/HD) + 1e-6f) * 0.125f;  // fold 1/sqrt(HD)
    a = a*sc*qn_w[l]; b = b*sc*qn_w[l+32];
    float inv = __expf(-(float)l*(1.f/32.f)*9.210340371976184f);
    float s, c; sincosf((float)t*inv, &s, &c);
    long long base = ((long long)h*L + t)*HD;
    g_qr[base + l]      = a*c - b*s;
    g_qr[base + l + 32] = b*c + a*s;
}

__global__ void kvrope_kernel(const float* __restrict__ kn_w){
    int t = blockIdx.x;
    int w = threadIdx.x >> 5, l = threadIdx.x & 31;
    if (w < 8){
        int j = w;
        float a = g_klin[(long long)t*(KVH*HD) + j*HD + l];
        float b = g_klin[(long long)t*(KVH*HD) + j*HD + l + 32];
        float ss = warpSum(a*a + b*b);
        float sc = rsqrtf(ss*(1.f/HD) + 1e-6f);
        a = a*sc*kn_w[l]; b = b*sc*kn_w[l+32];
        float inv = __expf(-(float)l*(1.f/32.f)*9.210340371976184f);
        float s, c; sincosf((float)t*inv, &s, &c);
        float o1 = a*c - b*s;
        float o2 = b*c + a*s;
        #pragma unroll
        for (int r = 0; r < 2; r++){
            long long base = ((long long)(2*j + r)*L + t)*HD;
            g_kr[base + l]      = o1;
            g_kr[base + l + 32] = o2;
        }
    } else {
        int j = w - 8;
        float a = g_vlin[(long long)t*(KVH*HD) + j*HD + l];
        float b = g_vlin[(long long)t*(KVH*HD) + j*HD + l + 32];
        #pragma unroll
        for (int r = 0; r < 2; r++){
            long long hb = (long long)(2*j + r)*HD;
            g_vt[(hb + l)*L + t]      = a;
            g_vt[(hb + l + 32)*L + t] = b;
        }
    }
}

__global__ void softmax_kernel(){
    float* row = g_scores + (long long)blockIdx.x*L;
    __shared__ float sred[8];
    int tid = threadIdx.x;
    float mx = -1e30f;
    for (int i = tid; i < L; i += 256) mx = fmaxf(mx, row[i]);
    #pragma unroll
    for (int o = 16; o; o >>= 1) mx = fmaxf(mx, __shfl_xor_sync(0xffffffffu, mx, o));
    if ((tid & 31) == 0) sred[tid >> 5] = mx;
    __syncthreads();
    if (tid == 0){ float m = sred[0]; for (int i = 1; i < 8; i++) m = fmaxf(m, sred[i]); sred[0] = m; }
    __syncthreads();
    mx = sred[0];
    __syncthreads();
    float s = 0.f;
    for (int i = tid; i < L; i += 256){ float e = __expf(row[i] - mx); row[i] = e; s += e; }
    s = warpSum(s);
    if ((tid & 31) == 0) sred[tid >> 5] = s;
    __syncthreads();
    if (tid == 0){ float t2 = 0.f; for (int i = 0; i < 8; i++) t2 += sred[i]; sred[0] = 1.f/t2; }
    __syncthreads();
    float inv = sred[0];
    for (int i = tid; i < L; i += 256) row[i] *= inv;
}

__global__ void conv_silu_kernel(const float* __restrict__ dww, const float* __restrict__ dwb){
    int t = blockIdx.x;
    for (int d = threadIdx.x; d < D; d += 256){
        float v = g_xn[(long long)t*D + d]*dww[d*3+1] + dwb[d];
        if (t > 0)     v += g_xn[(long long)(t-1)*D + d]*dww[d*3+0];
        if (t < L-1)   v += g_xn[(long long)(t+1)*D + d]*dww[d*3+2];
        g_convsilu[(long long)t*D + d] = v/(1.f + __expf(-v));
    }
}

__global__ void mix_kernel(const float* __restrict__ x, const float* __restrict__ mem){
    int t = blockIdx.x;
    float w0 = g_weights[t*4+0], w1 = g_weights[t*4+1];
    float w2 = g_weights[t*4+2], w3 = g_weights[t*4+3];
    for (int d = threadIdx.x; d < D; d += 256){
        long long i = (long long)t*D + d;
        g_x2[i] = x[i] + w0*g_outssm[i] + w1*g_outattn[i] + w2*g_outconv[i] + w3*mem[i];
    }
}

__global__ void gate_kernel(const float* __restrict__ n2w, const float* __restrict__ gw){
    int t = blockIdx.x;
    __shared__ float sred[8];
    __shared__ float sacc[8][8];
    __shared__ float sscale;
    const float* row = g_x2 + (long long)t*D;
    float ss = 0.f;
    for (int d = threadIdx.x; d < D; d += 256){ float v = row[d]; ss += v*v; }
    ss = warpSum(ss);
    if ((threadIdx.x & 31) == 0) sred[threadIdx.x >> 5] = ss;
    __syncthreads();
    if (threadIdx.x == 0){
        float s = 0.f; for (int i = 0; i < 8; i++) s += sred[i];
        sscale = rsqrtf(s*(1.f/D) + 1e-6f);
    }
    __syncthreads();
    float sc = sscale;
    float acc[8] = {0,0,0,0,0,0,0,0};
    for (int d = threadIdx.x; d < D; d += 256){
        float xv = row[d]*sc*n2w[d];
        #pragma unroll
        for (int e = 0; e < 8; e++) acc[e] += xv*gw[e*D + d];
    }
    #pragma unroll
    for (int e = 0; e < 8; e++) acc[e] = warpSum(acc[e]);
    if ((threadIdx.x & 31) == 0){
        #pragma unroll
        for (int e = 0; e < 8; e++) sacc[threadIdx.x >> 5][e] = acc[e];
    }
    __syncthreads();
    if (threadIdx.x == 0){
        float lg[8];
        #pragma unroll
        for (int e = 0; e < 8; e++){ float s = 0.f; for (int w2 = 0; w2 < 8; w2++) s += sacc[w2][e]; lg[e] = s; }
        float v1 = -1e30f; int i1 = 0;
        for (int e = 0; e < 8; e++) if (lg[e] > v1){ v1 = lg[e]; i1 = e; }
        float v2 = -1e30f; int i2 = 0;
        for (int e = 0; e < 8; e++) if (e != i1 && lg[e] > v2){ v2 = lg[e]; i2 = e; }
        g_vals[t*2+0] = v1; g_vals[t*2+1] = v2;
        g_topidx[t*2+0] = i1; g_topidx[t*2+1] = i2;
    }
}

__global__ void colsoftmax_kernel(){
    int i = blockIdx.x;       // slot 0/1
    int t = threadIdx.x;      // 1024 threads = 32 warps
    __shared__ float red[32];
    float v = g_vals[t*2 + i];
    float m = v;
    #pragma unroll
    for (int o = 16; o; o >>= 1) m = fmaxf(m, __shfl_xor_sync(0xffffffffu, m, o));
    if ((t & 31) == 0) red[t >> 5] = m;
    __syncthreads();
    if (t == 0){ float mm = red[0]; for (int k = 1; k < 32; k++) mm = fmaxf(mm, red[k]); red[0] = mm; }
    __syncthreads();
    m = red[0];
    __syncthreads();
    float e = __expf(v - m);
    float s = e;
    #pragma unroll
    for (int o = 16; o; o >>= 1) s += __shfl_xor_sync(0xffffffffu, s, o);
    if ((t & 31) == 0) red[t >> 5] = s;
    __syncthreads();
    if (t == 0){ float sm = 0.f; for (int k = 0; k < 32; k++) sm += red[k]; red[0] = sm; }
    __syncthreads();
    float w = e / red[0];
    if (i == 0) g_w0[t] = w; else g_w1[t] = w;
}

__global__ void zero_cnt_kernel(){
    if (threadIdx.x < E) g_cnt[threadIdx.x] = 0;
}

__global__ void compact_kernel(){
    int t = blockIdx.x*256 + threadIdx.x;
    if (t >= L) return;
    #pragma unroll
    for (int i = 0; i < 2; i++){
        int e = g_topidx[t*2 + i];
        int p = atomicAdd(&g_cnt[e], 1);
        g_tok[e*L + p] = t;
        g_slot[e*L + p] = i;
    }
}

__global__ void silumul_kernel(int e){
    int cnt = g_cnt[e];
    long long idx = (long long)blockIdx.x*256 + threadIdx.x;
    long long r = idx / HID;
    if (r >= cnt) return;
    long long c = idx % HID;
    float a = g_h1[r*2*HID + c];
    float g = g_h1[r*2*HID + HID + c];
    g_hh[r*HID + c] = a/(1.f + __expf(-a))*g;
}

__global__ void final_kernel(float* __restrict__ out){
    int t = blockIdx.x;
    for (int d = threadIdx.x; d < D; d += 256){
        long long i = (long long)t*D + d;
        out[i] = g_x2[i] + 0.1f*(g_moe[i] + g_moe[(long long)L*D + i]);
    }
}

// ------------------ launch ------------------
static inline dim3 ggrid(int M, int N, int Z){ return dim3((N+BN-1)/BN, (M+BM-1)/BM, Z); }

extern "C" void kernel_launch(void* const* d_in, const int* in_sizes, int n_in,
                              void* d_out, int out_size)
{
    const float* x         = (const float*)d_in[0];
    const float* mem       = (const float*)d_in[1];
    const float* norm1_w   = (const float*)d_in[2];
    const float* router_w  = (const float*)d_in[3];
    const float* ssm_norm_w= (const float*)d_in[4];
    const float* x_proj_w  = (const float*)d_in[5];
    const float* dt_proj_w = (const float*)d_in[6];
    const float* dt_proj_b = (const float*)d_in[7];
    const float* A_log     = (const float*)d_in[8];
    const float* D_param   = (const float*)d_in[9];
    const float* ssm_out_w = (const float*)d_in[10];
    const float* sel_w     = (const float*)d_in[11];
    const float* sel_b     = (const float*)d_in[12];
    const float* sel_gate  = (const float*)d_in[13];
    const float* q_w       = (const float*)d_in[14];
    const float* k_w       = (const float*)d_in[15];
    const float* v_w       = (const float*)d_in[16];
    const float* o_w       = (const float*)d_in[17];
    const float* qn_w      = (const float*)d_in[18];
    const float* kn_w      = (const float*)d_in[19];
    const float* dw_w      = (const float*)d_in[20];
    const float* dw_b      = (const float*)d_in[21];
    const float* pw_w      = (const float*)d_in[22];
    const float* pw_b      = (const float*)d_in[23];
    const float* norm2_w   = (const float*)d_in[24];
    const float* gate_w    = (const float*)d_in[25];
    const float* e_w1      = (const float*)d_in[26];
    const float* e_w2      = (const float*)d_in[27];
    const float* e_lw      = (const float*)d_in[28];
    const float* e_lb      = (const float*)d_in[29];
    float* out = (float*)d_out;

    float *p_xn, *p_sn, *p_snsel, *p_proj, *p_delta, *p_tmpssm, *p_outssm;
    float *p_qlin, *p_klin, *p_vlin, *p_qr, *p_kr, *p_vt, *p_scores, *p_attnout;
    float *p_outattn, *p_convsilu, *p_outconv, *p_x2, *p_h1, *p_hh, *p_y;
    cudaGetSymbolAddress((void**)&p_xn, g_xn);
    cudaGetSymbolAddress((void**)&p_sn, g_sn);
    cudaGetSymbolAddress((void**)&p_snsel, g_snsel);
    cudaGetSymbolAddress((void**)&p_proj, g_proj);
    cudaGetSymbolAddress((void**)&p_delta, g_delta);
    cudaGetSymbolAddress((void**)&p_tmpssm, g_tmpssm);
    cudaGetSymbolAddress((void**)&p_outssm, g_outssm);
    cudaGetSymbolAddress((void**)&p_qlin, g_qlin);
    cudaGetSymbolAddress((void**)&p_klin, g_klin);
    cudaGetSymbolAddress((void**)&p_vlin, g_vlin);
    cudaGetSymbolAddress((void**)&p_qr, g_qr);
    cudaGetSymbolAddress((void**)&p_kr, g_kr);
    cudaGetSymbolAddress((void**)&p_vt, g_vt);
    cudaGetSymbolAddress((void**)&p_scores, g_scores);
    cudaGetSymbolAddress((void**)&p_attnout, g_attnout);
    cudaGetSymbolAddress((void**)&p_outattn, g_outattn);
    cudaGetSymbolAddress((void**)&p_convsilu, g_convsilu);
    cudaGetSymbolAddress((void**)&p_outconv, g_outconv);
    cudaGetSymbolAddress((void**)&p_x2, g_x2);
    cudaGetSymbolAddress((void**)&p_h1, g_h1);
    cudaGetSymbolAddress((void**)&p_hh, g_hh);
    cudaGetSymbolAddress((void**)&p_y, g_y);

    // 1. xn = rms(x, norm1_w); router
    rms_kernel<<<L, 256>>>(x, norm1_w, p_xn);
    router_kernel<<<L, 256>>>(router_w);
    // 2. sn = rms(xn, ssm_norm_w)
    rms_kernel<<<L, 256>>>(p_xn, ssm_norm_w, p_sn);
    // 3. sn_sel = sn * sigmoid((sn@sel_w.T + sel_b)*sel_gate)
    gemm_nt<3,false><<<ggrid(L, D, 1), 256>>>(p_sn, sel_w, p_snsel, L, D, D, D, D, D,
        0, 0, 0, sel_b, p_sn, sel_gate, -1);
    // 4. proj = sn_sel @ x_proj_w.T
    gemm_nt<0,false><<<ggrid(L, PRJ, 1), 256>>>(p_snsel, x_proj_w, p_proj, L, PRJ, D, D, D, PRJ,
        0, 0, 0, nullptr, nullptr, nullptr, -1);
    // 5. delta = softplus(proj[:, :DT] @ dt_proj_w.T + dt_proj_b)
    gemm_nt<2,false><<<ggrid(L, D, 1), 256>>>(p_proj, dt_proj_w, p_delta, L, D, DT, PRJ, DT, D,
        0, 0, 0, dt_proj_b, nullptr, nullptr, -1);
    // 6. SSM scan (+ xn*D_param folded)
    scan_kernel<<<D/4, 128>>>(A_log, D_param);
    // 7. out_ssm
    gemm_nt<0,false><<<ggrid(L, D, 1), 256>>>(p_tmpssm, ssm_out_w, p_outssm, L, D, D, D, D, D,
        0, 0, 0, nullptr, nullptr, nullptr, -1);
    // 8. q/k/v projections
    gemm_nt<0,false><<<ggrid(L, D, 1), 256>>>(p_xn, q_w, p_qlin, L, D, D, D, D, D,
        0, 0, 0, nullptr, nullptr, nullptr, -1);
    gemm_nt<0,false><<<ggrid(L, KVH*HD, 1), 256>>>(p_xn, k_w, p_klin, L, KVH*HD, D, D, D, KVH*HD,
        0, 0, 0, nullptr, nullptr, nullptr, -1);
    gemm_nt<0,false><<<ggrid(L, KVH*HD, 1), 256>>>(p_xn, v_w, p_vlin, L, KVH*HD, D, D, D, KVH*HD,
        0, 0, 0, nullptr, nullptr, nullptr, -1);
    // 9. rms + rope (+GQA repeat, v transpose)
    qrope_kernel<<<L, 512>>>(qn_w);
    kvrope_kernel<<<L, 512>>>(kn_w);
    // 10. scores = q@k^T (scale folded into q), batched over heads
    gemm_nt<0,false><<<ggrid(L, L, H), 256>>>(p_qr, p_kr, p_scores, L, L, HD, HD, HD, L,
        (long long)L*HD, (long long)L*HD, (long long)L*L, nullptr, nullptr, nullptr, -1);
    // 11. softmax rows
    softmax_kernel<<<H*L, 256>>>();
    // 12. attn @ v  (v transposed: NT)
    gemm_nt<0,false><<<ggrid(L, HD, H), 256>>>(p_scores, p_vt, p_attnout, L, HD, L, L, L, D,
        (long long)L*L, (long long)HD*L, (long long)HD, nullptr, nullptr, nullptr, -1);
    // 13. out_attn
    gemm_nt<0,false><<<ggrid(L, D, 1), 256>>>(p_attnout, o_w, p_outattn, L, D, D, D, D, D,
        0, 0, 0, nullptr, nullptr, nullptr, -1);
    // 14. conv + silu, then pointwise
    conv_silu_kernel<<<L, 256>>>(dw_w, dw_b);
    gemm_nt<1,false><<<ggrid(L, D, 1), 256>>>(p_convsilu, pw_w, p_outconv, L, D, D, D, D, D,
        0, 0, 0, pw_b, nullptr, nullptr, -1);
    // 15. mix -> x2
    mix_kernel<<<L, 256>>>(x, mem);
    // 16. gate logits + top2; sequence-wide softmax of top-k vals; compaction
    gate_kernel<<<L, 256>>>(norm2_w, gate_w);
    colsoftmax_kernel<<<2, 1024>>>();
    zero_cnt_kernel<<<1, 32>>>();
    compact_kernel<<<(L+255)/256, 256>>>();
    // 17. routed experts (fixed worst-case grids; early-exit on g_cnt[e])
    for (int e = 0; e < E; e++){
        gemm_nt<0,true><<<ggrid(L, 2*HID, 1), 256>>>(p_x2, e_w1 + (long long)e*2*HID*D, p_h1,
            L, 2*HID, D, D, D, 2*HID, 0, 0, 0, nullptr, nullptr, nullptr, e);
        silumul_kernel<<<(L*HID)/256, 256>>>(e);
        gemm_nt<0,false><<<ggrid(L, D, 1), 256>>>(p_hh, e_w2 + (long long)e*D*HID, p_y,
            L, D, HID, HID, HID, D, 0, 0, 0, nullptr, nullptr, nullptr, e);
        gemm_nt<5,false><<<ggrid(L, D, 1), 256>>>(p_y, e_lw + (long long)e*D*D, p_y,
            L, D, D, D, D, D, 0, 0, 0, e_lb + (long long)e*D, nullptr, nullptr, e);
    }
    // 18. out = x2 + 0.1*moe
    final_kernel<<<L, 256>>>(out);
}

// round 3
// speedup vs baseline: 4.4507x; 4.4507x over previous
#include <cuda_runtime.h>
#include <math.h>

namespace {
constexpr int L   = 1024;
constexpr int D   = 1024;
constexpr int H   = 16;
constexpr int KVH = 8;
constexpr int HD  = 64;
constexpr int NS  = 128;
constexpr int DT  = 64;
constexpr int E   = 8;
constexpr int HID = 4096;
constexpr int PRJ = DT + 2*NS; // 320
constexpr int BM = 128, BN = 128, BK = 16;
}

// ------------------ scratch: device globals (allocation-free) ------------------
__device__ float g_xn[L*D];
__device__ float g_sn[L*D];
__device__ float g_snsel[L*D];
__device__ float g_proj[L*PRJ];
__device__ float g_delta[L*D];
__device__ float g_tmpssm[L*D];
__device__ float g_outssm[L*D];
__device__ float g_qlin[L*D];
__device__ float g_klin[L*KVH*HD];
__device__ float g_vlin[L*KVH*HD];
__device__ float g_qr[H*L*HD];
__device__ float g_kr[H*L*HD];
__device__ float g_vt[H*HD*L];
__device__ float g_scores[H*L*L];
__device__ float g_attnout[L*D];
__device__ float g_outattn[L*D];
__device__ float g_convsilu[L*D];
__device__ float g_outconv[L*D];
__device__ float g_weights[L*4];
__device__ float g_x2[L*D];
__device__ float g_vals[L*2];
__device__ int   g_topidx[L*2];
__device__ float g_w0[L];
__device__ float g_w1[L];
__device__ int   g_cnt[E];
__device__ int   g_tok[E*L];
__device__ int   g_slot[E*L];
__device__ float g_h1[(long long)E*L*2*HID];   // 256 MB worst case
__device__ float g_hh[(long long)E*L*HID];     // 128 MB
__device__ float g_y [(long long)E*L*D];       // 32 MB
__device__ float g_moe[2*L*D];

__device__ __forceinline__ float warpSum(float v){
    #pragma unroll
    for (int o = 16; o; o >>= 1) v += __shfl_xor_sync(0xffffffffu, v, o);
    return v;
}

__device__ __forceinline__ unsigned f2tf(float x){
    unsigned r; asm("cvt.rna.tf32.f32 %0, %1;" : "=r"(r) : "f"(x)); return r;
}
__device__ __forceinline__ float4 cv4(float4 v){
    v.x = __uint_as_float(f2tf(v.x));
    v.y = __uint_as_float(f2tf(v.y));
    v.z = __uint_as_float(f2tf(v.z));
    v.w = __uint_as_float(f2tf(v.w));
    return v;
}
__device__ __forceinline__ void mma8(float* d, const unsigned* a, const unsigned* b){
    asm volatile(
      "mma.sync.aligned.m16n8k8.row.col.f32.tf32.tf32.f32 "
      "{%0,%1,%2,%3},{%4,%5,%6,%7},{%8,%9},{%0,%1,%2,%3};"
      : "+f"(d[0]), "+f"(d[1]), "+f"(d[2]), "+f"(d[3])
      : "r"(a[0]), "r"(a[1]), "r"(a[2]), "r"(a[3]), "r"(b[0]), "r"(b[1]));
}

// ------------------ tf32 tensor-core NT GEMM: C[m,n] = sum_k A[m,k]*B[n,k] ----
// EPI: 0 none | 1 +x0[n] | 2 softplus(acc+x0[n]) | 3 x1[m*ldc+n]*sigmoid((acc+x0[n])*x2p[n])
//      | 5 MoE scatter: g_moe[(slot*L+tok)*D+n] = w_slot[tok]*(acc + x0[e*D+n])
// eidx >= 0: expert e=eidx, M=g_cnt[e].  eidx == -2: e=blockIdx.z (batched experts).
// GATHER: A row = g_tok[e*L + row].
template<int EPI, bool GATHER>
__global__ void __launch_bounds__(256, 1)
gemm_tc(const float* __restrict__ A, const float* __restrict__ B, float* __restrict__ Cp,
        int M, int N, int K, int lda, int ldb, int ldc,
        long long sA, long long sB, long long sC,
        const float* __restrict__ x0, const float* __restrict__ x1,
        const float* __restrict__ x2p, int eidx)
{
    __shared__ float As[2][BM][BK+4];
    __shared__ float Bs[2][BN][BK+4];

    int bm = blockIdx.y, bn = blockIdx.x, bz = blockIdx.z;
    int e = eidx;
    if (eidx == -2) e = bz;
    if (e >= 0) M = g_cnt[e];
    int row0 = bm*BM, col0 = bn*BN;
    if (row0 >= M) return;
    A += bz*sA; B += bz*sB; Cp += bz*sC;

    int tid = threadIdx.x;
    int lane = tid & 31, warp = tid >> 5;
    int wm = warp >> 2, wn = warp & 3;          // 2x4 warp grid, warp tile 64x32
    int g  = lane >> 2, t4 = lane & 3;

    // global->smem loader assignments: 2 rows per thread, float4 columns
    int lr0 = tid >> 2;            // 0..63
    int lr1 = lr0 + 64;
    int lc  = (tid & 3)*4;         // 0,4,8,12

    long long asrc0 = -1, asrc1 = -1;
    {
        int am0 = row0 + lr0, am1 = row0 + lr1;
        if (am0 < M) asrc0 = GATHER ? g_tok[e*L + am0] : am0;
        if (am1 < M) asrc1 = GATHER ? g_tok[e*L + am1] : am1;
    }
    int bn0 = col0 + lr0, bn1 = col0 + lr1;
    bool bv0 = bn0 < N, bv1 = bn1 < N;

    const float4 z4 = make_float4(0.f,0.f,0.f,0.f);
    float acc[4][4][4];
    #pragma unroll
    for (int i = 0; i < 4; i++)
        #pragma unroll
        for (int j = 0; j < 4; j++)
            #pragma unroll
            for (int c = 0; c < 4; c++) acc[i][j][c] = 0.f;

    float4 ra0, ra1, rb0, rb1;
    // prologue: load tile 0
    ra0 = (asrc0 >= 0) ? *(const float4*)(A + asrc0*lda + lc) : z4;
    ra1 = (asrc1 >= 0) ? *(const float4*)(A + asrc1*lda + lc) : z4;
    rb0 = bv0 ? *(const float4*)(B + (long long)bn0*ldb + lc) : z4;
    rb1 = bv1 ? *(const float4*)(B + (long long)bn1*ldb + lc) : z4;
    *(float4*)&As[0][lr0][lc] = cv4(ra0);
    *(float4*)&As[0][lr1][lc] = cv4(ra1);
    *(float4*)&Bs[0][lr0][lc] = cv4(rb0);
    *(float4*)&Bs[0][lr1][lc] = cv4(rb1);
    __syncthreads();

    int NT = K / BK;
    for (int kt = 0; kt < NT; kt++){
        int cur = kt & 1;
        if (kt + 1 < NT){
            int k0 = (kt+1)*BK;
            ra0 = (asrc0 >= 0) ? *(const float4*)(A + asrc0*lda + k0 + lc) : z4;
            ra1 = (asrc1 >= 0) ? *(const float4*)(A + asrc1*lda + k0 + lc) : z4;
            rb0 = bv0 ? *(const float4*)(B + (long long)bn0*ldb + k0 + lc) : z4;
            rb1 = bv1 ? *(const float4*)(B + (long long)bn1*ldb + k0 + lc) : z4;
        }
        #pragma unroll
        for (int kp = 0; kp < 2; kp++){
            int kb = kp*8;
            unsigned a[4][4], b[4][2];
            #pragma unroll
            for (int mt = 0; mt < 4; mt++){
                int m = wm*64 + mt*16 + g;
                a[mt][0] = __float_as_uint(As[cur][m  ][kb + t4]);
                a[mt][1] = __float_as_uint(As[cur][m+8][kb + t4]);
                a[mt][2] = __float_as_uint(As[cur][m  ][kb + t4 + 4]);
                a[mt][3] = __float_as_uint(As[cur][m+8][kb + t4 + 4]);
            }
            #pragma unroll
            for (int nt = 0; nt < 4; nt++){
                int n = wn*32 + nt*8 + g;
                b[nt][0] = __float_as_uint(Bs[cur][n][kb + t4]);
                b[nt][1] = __float_as_uint(Bs[cur][n][kb + t4 + 4]);
            }
            #pragma unroll
            for (int mt = 0; mt < 4; mt++)
                #pragma unroll
                for (int nt = 0; nt < 4; nt++)
                    mma8(acc[mt][nt], a[mt], b[nt]);
        }
        if (kt + 1 < NT){
            int nxt = cur ^ 1;
            *(float4*)&As[nxt][lr0][lc] = cv4(ra0);
            *(float4*)&As[nxt][lr1][lc] = cv4(ra1);
            *(float4*)&Bs[nxt][lr0][lc] = cv4(rb0);
            *(float4*)&Bs[nxt][lr1][lc] = cv4(rb1);
        }
        __syncthreads();
    }

    // epilogue
    int mbase = row0 + wm*64, nbase = col0 + wn*32;
    #pragma unroll
    for (int mt = 0; mt < 4; mt++){
        #pragma unroll
        for (int nt = 0; nt < 4; nt++){
            #pragma unroll
            for (int c = 0; c < 4; c++){
                int m = mbase + mt*16 + g + (c >= 2 ? 8 : 0);
                int n = nbase + nt*8 + t4*2 + (c & 1);
                if (m >= M || n >= N) continue;
                float v = acc[mt][nt][c];
                if (EPI == 0){
                    Cp[(long long)m*ldc + n] = v;
                } else if (EPI == 1){
                    Cp[(long long)m*ldc + n] = v + x0[n];
                } else if (EPI == 2){
                    float zz = v + x0[n];
                    Cp[(long long)m*ldc + n] = fmaxf(zz, 0.f) + log1pf(__expf(-fabsf(zz)));
                } else if (EPI == 3){
                    float zz = (v + x0[n]) * x2p[n];
                    Cp[(long long)m*ldc + n] = x1[(long long)m*ldc + n] / (1.f + __expf(-zz));
                } else if (EPI == 5){
                    int tok = g_tok[e*L + m];
                    int sl  = g_slot[e*L + m];
                    float w = sl ? g_w1[tok] : g_w0[tok];
                    g_moe[((long long)sl*L + tok)*D + n] = w * (v + x0[(long long)e*D + n]);
                }
            }
        }
    }
}

// ------------------ elementwise / reduction kernels ------------------
__global__ void rms_kernel(const float* __restrict__ in, const float* __restrict__ w,
                           float* __restrict__ out){
    int t = blockIdx.x;
    const float* row = in + (long long)t*D;
    __shared__ float sred[8];
    __shared__ float sscale;
    float ss = 0.f;
    for (int d = threadIdx.x; d < D; d += 256){ float v = row[d]; ss += v*v; }
    ss = warpSum(ss);
    if ((threadIdx.x & 31) == 0) sred[threadIdx.x >> 5] = ss;
    __syncthreads();
    if (threadIdx.x == 0){
        float s = 0.f;
        #pragma unroll
        for (int i = 0; i < 8; i++) s += sred[i];
        sscale = rsqrtf(s*(1.f/D) + 1e-6f);
    }
    __syncthreads();
    float sc = sscale;
    for (int d = threadIdx.x; d < D; d += 256)
        out[(long long)t*D + d] = row[d]*sc*w[d];
}

__global__ void router_kernel(const float* __restrict__ rw){
    int t = blockIdx.x;
    __shared__ float sm[8][4];
    float acc[4] = {0,0,0,0};
    for (int d = threadIdx.x; d < D; d += 256){
        float xv = g_xn[(long long)t*D + d];
        #pragma unroll
        for (int j = 0; j < 4; j++) acc[j] += xv*rw[j*D + d];
    }
    #pragma unroll
    for (int j = 0; j < 4; j++) acc[j] = warpSum(acc[j]);
    if ((threadIdx.x & 31) == 0){
        #pragma unroll
        for (int j = 0; j < 4; j++) sm[threadIdx.x >> 5][j] = acc[j];
    }
    __syncthreads();
    if (threadIdx.x == 0){
        float lg[4];
        #pragma unroll
        for (int j = 0; j < 4; j++){ float s = 0.f; for (int w2 = 0; w2 < 8; w2++) s += sm[w2][j]; lg[j] = s; }
        float mx = fmaxf(fmaxf(lg[0], lg[1]), fmaxf(lg[2], lg[3]));
        float sum = 0.f;
        #pragma unroll
        for (int j = 0; j < 4; j++){ lg[j] = __expf(lg[j] - mx); sum += lg[j]; }
        const float c[4] = {0.5f, 0.2f, 0.15f, 0.15f};
        float s2 = 0.f;
        #pragma unroll
        for (int j = 0; j < 4; j++){ lg[j] = lg[j]/sum*c[j]; s2 += lg[j]; }
        #pragma unroll
        for (int j = 0; j < 4; j++) g_weights[t*4 + j] = lg[j]/s2;
    }
}

__global__ void scan_kernel(const float* __restrict__ A_log, const float* __restrict__ Dp){
    int w = threadIdx.x >> 5, lane = threadIdx.x & 31;
    int d = blockIdx.x*4 + w;
    float A0[4], h[4] = {0,0,0,0};
    #pragma unroll
    for (int i = 0; i < 4; i++) A0[i] = -__expf(A_log[d*NS + lane + 32*i]);
    float Dpd = Dp[d];
    for (int t = 0; t < L; t++){
        float dt = g_delta[(long long)t*D + d];
        float xt = g_snsel[(long long)t*D + d];
        float dx = dt*xt;
        float acc = 0.f;
        #pragma unroll
        for (int i = 0; i < 4; i++){
            float b = g_proj[(long long)t*PRJ + DT + lane + 32*i];
            float c = g_proj[(long long)t*PRJ + DT + NS + lane + 32*i];
            h[i] = __expf(dt*A0[i])*h[i] + dx*b;
            acc += h[i]*c;
        }
        acc = warpSum(acc);
        if (lane == 0)
            g_tmpssm[(long long)t*D + d] = acc + g_xn[(long long)t*D + d]*Dpd;
    }
}

__global__ void qrope_kernel(const float* __restrict__ qn_w){
    int t = blockIdx.x;
    int h = threadIdx.x >> 5, l = threadIdx.x & 31;
    float a = g_qlin[(long long)t*D + h*HD + l];
    float b = g_qlin[(long long)t*D + h*HD + l + 32];
    float ss = warpSum(a*a + b*b);
    float sc = rsqrtf(ss*(1.f/HD) + 1e-6f) * 0.125f;  // fold 1/sqrt(HD)
    a = a*sc*qn_w[l]; b = b*sc*qn_w[l+32];
    float inv = __expf(-(float)l*(1.f/32.f)*9.210340371976184f);
    float s, c; sincosf((float)t*inv, &s, &c);
    long long base = ((long long)h*L + t)*HD;
    g_qr[base + l]      = a*c - b*s;
    g_qr[base + l + 32] = b*c + a*s;
}

__global__ void kvrope_kernel(const float* __restrict__ kn_w){
    int t = blockIdx.x;
    int w = threadIdx.x >> 5, l = threadIdx.x & 31;
    if (w < 8){
        int j = w;
        float a = g_klin[(long long)t*(KVH*HD) + j*HD + l];
        float b = g_klin[(long long)t*(KVH*HD) + j*HD + l + 32];
        float ss = warpSum(a*a + b*b);
        float sc = rsqrtf(ss*(1.f/HD) + 1e-6f);
        a = a*sc*kn_w[l]; b = b*sc*kn_w[l+32];
        float inv = __expf(-(float)l*(1.f/32.f)*9.210340371976184f);
        float s, c; sincosf((float)t*inv, &s, &c);
        float o1 = a*c - b*s;
        float o2 = b*c + a*s;
        #pragma unroll
        for (int r = 0; r < 2; r++){
            long long base = ((long long)(2*j + r)*L + t)*HD;
            g_kr[base + l]      = o1;
            g_kr[base + l + 32] = o2;
        }
    } else {
        int j = w - 8;
        float a = g_vlin[(long long)t*(KVH*HD) + j*HD + l];
        float b = g_vlin[(long long)t*(KVH*HD) + j*HD + l + 32];
        #pragma unroll
        for (int r = 0; r < 2; r++){
            long long hb = (long long)(2*j + r)*HD;
            g_vt[(hb + l)*L + t]      = a;
            g_vt[(hb + l + 32)*L + t] = b;
        }
    }
}

__global__ void softmax_kernel(){
    float* row = g_scores + (long long)blockIdx.x*L;
    __shared__ float sred[8];
    int tid = threadIdx.x;
    float mx = -1e30f;
    for (int i = tid; i < L; i += 256) mx = fmaxf(mx, row[i]);
    #pragma unroll
    for (int o = 16; o; o >>= 1) mx = fmaxf(mx, __shfl_xor_sync(0xffffffffu, mx, o));
    if ((tid & 31) == 0) sred[tid >> 5] = mx;
    __syncthreads();
    if (tid == 0){ float m = sred[0]; for (int i = 1; i < 8; i++) m = fmaxf(m, sred[i]); sred[0] = m; }
    __syncthreads();
    mx = sred[0];
    __syncthreads();
    float s = 0.f;
    for (int i = tid; i < L; i += 256){ float e = __expf(row[i] - mx); row[i] = e; s += e; }
    s = warpSum(s);
    if ((tid & 31) == 0) sred[tid >> 5] = s;
    __syncthreads();
    if (tid == 0){ float t2 = 0.f; for (int i = 0; i < 8; i++) t2 += sred[i]; sred[0] = 1.f/t2; }
    __syncthreads();
    float inv = sred[0];
    for (int i = tid; i < L; i += 256) row[i] *= inv;
}

__global__ void conv_silu_kernel(const float* __restrict__ dww, const float* __restrict__ dwb){
    int t = blockIdx.x;
    for (int d = threadIdx.x; d < D; d += 256){
        float v = g_xn[(long long)t*D + d]*dww[d*3+1] + dwb[d];
        if (t > 0)     v += g_xn[(long long)(t-1)*D + d]*dww[d*3+0];
        if (t < L-1)   v += g_xn[(long long)(t+1)*D + d]*dww[d*3+2];
        g_convsilu[(long long)t*D + d] = v/(1.f + __expf(-v));
    }
}

__global__ void mix_kernel(const float* __restrict__ x, const float* __restrict__ mem){
    int t = blockIdx.x;
    float w0 = g_weights[t*4+0], w1 = g_weights[t*4+1];
    float w2 = g_weights[t*4+2], w3 = g_weights[t*4+3];
    for (int d = threadIdx.x; d < D; d += 256){
        long long i = (long long)t*D + d;
        g_x2[i] = x[i] + w0*g_outssm[i] + w1*g_outattn[i] + w2*g_outconv[i] + w3*mem[i];
    }
}

__global__ void gate_kernel(const float* __restrict__ n2w, const float* __restrict__ gw){
    int t = blockIdx.x;
    __shared__ float sred[8];
    __shared__ float sacc[8][8];
    __shared__ float sscale;
    const float* row = g_x2 + (long long)t*D;
    float ss = 0.f;
    for (int d = threadIdx.x; d < D; d += 256){ float v = row[d]; ss += v*v; }
    ss = warpSum(ss);
    if ((threadIdx.x & 31) == 0) sred[threadIdx.x >> 5] = ss;
    __syncthreads();
    if (threadIdx.x == 0){
        float s = 0.f; for (int i = 0; i < 8; i++) s += sred[i];
        sscale = rsqrtf(s*(1.f/D) + 1e-6f);
    }
    __syncthreads();
    float sc = sscale;
    float acc[8] = {0,0,0,0,0,0,0,0};
    for (int d = threadIdx.x; d < D; d += 256){
        float xv = row[d]*sc*n2w[d];
        #pragma unroll
        for (int e = 0; e < 8; e++) acc[e] += xv*gw[e*D + d];
    }
    #pragma unroll
    for (int e = 0; e < 8; e++) acc[e] = warpSum(acc[e]);
    if ((threadIdx.x & 31) == 0){
        #pragma unroll
        for (int e = 0; e < 8; e++) sacc[threadIdx.x >> 5][e] = acc[e];
    }
    __syncthreads();
    if (threadIdx.x == 0){
        float lg[8];
        #pragma unroll
        for (int e = 0; e < 8; e++){ float s = 0.f; for (int w2 = 0; w2 < 8; w2++) s += sacc[w2][e]; lg[e] = s; }
        float v1 = -1e30f; int i1 = 0;
        for (int e = 0; e < 8; e++) if (lg[e] > v1){ v1 = lg[e]; i1 = e; }
        float v2 = -1e30f; int i2 = 0;
        for (int e = 0; e < 8; e++) if (e != i1 && lg[e] > v2){ v2 = lg[e]; i2 = e; }
        g_vals[t*2+0] = v1; g_vals[t*2+1] = v2;
        g_topidx[t*2+0] = i1; g_topidx[t*2+1] = i2;
    }
}

__global__ void colsoftmax_kernel(){
    int i = blockIdx.x;
    int t = threadIdx.x;
    __shared__ float red[32];
    float v = g_vals[t*2 + i];
    float m = v;
    #pragma unroll
    for (int o = 16; o; o >>= 1) m = fmaxf(m, __shfl_xor_sync(0xffffffffu, m, o));
    if ((t & 31) == 0) red[t >> 5] = m;
    __syncthreads();
    if (t == 0){ float mm = red[0]; for (int k = 1; k < 32; k++) mm = fmaxf(mm, red[k]); red[0] = mm; }
    __syncthreads();
    m = red[0];
    __syncthreads();
    float e = __expf(v - m);
    float s = e;
    #pragma unroll
    for (int o = 16; o; o >>= 1) s += __shfl_xor_sync(0xffffffffu, s, o);
    if ((t & 31) == 0) red[t >> 5] = s;
    __syncthreads();
    if (t == 0){ float sm = 0.f; for (int k = 0; k < 32; k++) sm += red[k]; red[0] = sm; }
    __syncthreads();
    float w = e / red[0];
    if (i == 0) g_w0[t] = w; else g_w1[t] = w;
}

__global__ void zero_cnt_kernel(){
    if (threadIdx.x < E) g_cnt[threadIdx.x] = 0;
}

__global__ void compact_kernel(){
    int t = blockIdx.x*256 + threadIdx.x;
    if (t >= L) return;
    #pragma unroll
    for (int i = 0; i < 2; i++){
        int e = g_topidx[t*2 + i];
        int p = atomicAdd(&g_cnt[e], 1);
        g_tok[e*L + p] = t;
        g_slot[e*L + p] = i;
    }
}

// batched over experts: grid (L, E)
__global__ void silumul_kernel(){
    int e = blockIdx.y, r = blockIdx.x;
    if (r >= g_cnt[e]) return;
    const float* h = g_h1 + ((long long)e*L + r)*2*HID;
    float* o = g_hh + ((long long)e*L + r)*HID;
    for (int c = threadIdx.x; c < HID; c += 256){
        float a = h[c], g = h[HID + c];
        o[c] = a/(1.f + __expf(-a))*g;
    }
}

__global__ void final_kernel(float* __restrict__ out){
    int t = blockIdx.x;
    for (int d = threadIdx.x; d < D; d += 256){
        long long i = (long long)t*D + d;
        out[i] = g_x2[i] + 0.1f*(g_moe[i] + g_moe[(long long)L*D + i]);
    }
}

// ------------------ launch ------------------
static inline dim3 ggrid(int M, int N, int Z){ return dim3((N+BN-1)/BN, (M+BM-1)/BM, Z); }

extern "C" void kernel_launch(void* const* d_in, const int* in_sizes, int n_in,
                              void* d_out, int out_size)
{
    const float* x         = (const float*)d_in[0];
    const float* mem       = (const float*)d_in[1];
    const float* norm1_w   = (const float*)d_in[2];
    const float* router_w  = (const float*)d_in[3];
    const float* ssm_norm_w= (const float*)d_in[4];
    const float* x_proj_w  = (const float*)d_in[5];
    const float* dt_proj_w = (const float*)d_in[6];
    const float* dt_proj_b = (const float*)d_in[7];
    const float* A_log     = (const float*)d_in[8];
    const float* D_param   = (const float*)d_in[9];
    const float* ssm_out_w = (const float*)d_in[10];
    const float* sel_w     = (const float*)d_in[11];
    const float* sel_b     = (const float*)d_in[12];
    const float* sel_gate  = (const float*)d_in[13];
    const float* q_w       = (const float*)d_in[14];
    const float* k_w       = (const float*)d_in[15];
    const float* v_w       = (const float*)d_in[16];
    const float* o_w       = (const float*)d_in[17];
    const float* qn_w      = (const float*)d_in[18];
    const float* kn_w      = (const float*)d_in[19];
    const float* dw_w      = (const float*)d_in[20];
    const float* dw_b      = (const float*)d_in[21];
    const float* pw_w      = (const float*)d_in[22];
    const float* pw_b      = (const float*)d_in[23];
    const float* norm2_w   = (const float*)d_in[24];
    const float* gate_w    = (const float*)d_in[25];
    const float* e_w1      = (const float*)d_in[26];
    const float* e_w2      = (const float*)d_in[27];
    const float* e_lw      = (const float*)d_in[28];
    const float* e_lb      = (const float*)d_in[29];
    float* out = (float*)d_out;

    float *p_xn, *p_sn, *p_snsel, *p_proj, *p_delta, *p_tmpssm, *p_outssm;
    float *p_qlin, *p_klin, *p_vlin, *p_qr, *p_kr, *p_vt, *p_scores, *p_attnout;
    float *p_outattn, *p_convsilu, *p_outconv, *p_x2, *p_h1, *p_hh, *p_y;
    cudaGetSymbolAddress((void**)&p_xn, g_xn);
    cudaGetSymbolAddress((void**)&p_sn, g_sn);
    cudaGetSymbolAddress((void**)&p_snsel, g_snsel);
    cudaGetSymbolAddress((void**)&p_proj, g_proj);
    cudaGetSymbolAddress((void**)&p_delta, g_delta);
    cudaGetSymbolAddress((void**)&p_tmpssm, g_tmpssm);
    cudaGetSymbolAddress((void**)&p_outssm, g_outssm);
    cudaGetSymbolAddress((void**)&p_qlin, g_qlin);
    cudaGetSymbolAddress((void**)&p_klin, g_klin);
    cudaGetSymbolAddress((void**)&p_vlin, g_vlin);
    cudaGetSymbolAddress((void**)&p_qr, g_qr);
    cudaGetSymbolAddress((void**)&p_kr, g_kr);
    cudaGetSymbolAddress((void**)&p_vt, g_vt);
    cudaGetSymbolAddress((void**)&p_scores, g_scores);
    cudaGetSymbolAddress((void**)&p_attnout, g_attnout);
    cudaGetSymbolAddress((void**)&p_outattn, g_outattn);
    cudaGetSymbolAddress((void**)&p_convsilu, g_convsilu);
    cudaGetSymbolAddress((void**)&p_outconv, g_outconv);
    cudaGetSymbolAddress((void**)&p_x2, g_x2);
    cudaGetSymbolAddress((void**)&p_h1, g_h1);
    cudaGetSymbolAddress((void**)&p_hh, g_hh);
    cudaGetSymbolAddress((void**)&p_y, g_y);

    // 1. xn = rms(x); router
    rms_kernel<<<L, 256>>>(x, norm1_w, p_xn);
    router_kernel<<<L, 256>>>(router_w);
    // 2. sn = rms(xn)
    rms_kernel<<<L, 256>>>(p_xn, ssm_norm_w, p_sn);
    // 3. sn_sel = sn * sigmoid((sn@sel_w.T + sel_b)*sel_gate)
    gemm_tc<3,false><<<ggrid(L, D, 1), 256>>>(p_sn, sel_w, p_snsel, L, D, D, D, D, D,
        0, 0, 0, sel_b, p_sn, sel_gate, -1);
    // 4. proj
    gemm_tc<0,false><<<ggrid(L, PRJ, 1), 256>>>(p_snsel, x_proj_w, p_proj, L, PRJ, D, D, D, PRJ,
        0, 0, 0, nullptr, nullptr, nullptr, -1);
    // 5. delta = softplus(proj[:, :DT]@dt_w.T + b)
    gemm_tc<2,false><<<ggrid(L, D, 1), 256>>>(p_proj, dt_proj_w, p_delta, L, D, DT, PRJ, DT, D,
        0, 0, 0, dt_proj_b, nullptr, nullptr, -1);
    // 6. SSM scan (+ xn*D_param)
    scan_kernel<<<D/4, 128>>>(A_log, D_param);
    // 7. out_ssm
    gemm_tc<0,false><<<ggrid(L, D, 1), 256>>>(p_tmpssm, ssm_out_w, p_outssm, L, D, D, D, D, D,
        0, 0, 0, nullptr, nullptr, nullptr, -1);
    // 8. q/k/v
    gemm_tc<0,false><<<ggrid(L, D, 1), 256>>>(p_xn, q_w, p_qlin, L, D, D, D, D, D,
        0, 0, 0, nullptr, nullptr, nullptr, -1);
    gemm_tc<0,false><<<ggrid(L, KVH*HD, 1), 256>>>(p_xn, k_w, p_klin, L, KVH*HD, D, D, D, KVH*HD,
        0, 0, 0, nullptr, nullptr, nullptr, -1);
    gemm_tc<0,false><<<ggrid(L, KVH*HD, 1), 256>>>(p_xn, v_w, p_vlin, L, KVH*HD, D, D, D, KVH*HD,
        0, 0, 0, nullptr, nullptr, nullptr, -1);
    // 9. rms+rope (+GQA repeat, v transpose)
    qrope_kernel<<<L, 512>>>(qn_w);
    kvrope_kernel<<<L, 512>>>(kn_w);
    // 10. scores (scale folded into q), batched over heads
    gemm_tc<0,false><<<ggrid(L, L, H), 256>>>(p_qr, p_kr, p_scores, L, L, HD, HD, HD, L,
        (long long)L*HD, (long long)L*HD, (long long)L*L, nullptr, nullptr, nullptr, -1);
    // 11. softmax
    softmax_kernel<<<H*L, 256>>>();
    // 12. attn@v (v transposed: NT)
    gemm_tc<0,false><<<ggrid(L, HD, H), 256>>>(p_scores, p_vt, p_attnout, L, HD, L, L, L, D,
        (long long)L*L, (long long)HD*L, (long long)HD, nullptr, nullptr, nullptr, -1);
    // 13. out_attn
    gemm_tc<0,false><<<ggrid(L, D, 1), 256>>>(p_attnout, o_w, p_outattn, L, D, D, D, D, D,
        0, 0, 0, nullptr, nullptr, nullptr, -1);
    // 14. conv + silu, pointwise
    conv_silu_kernel<<<L, 256>>>(dw_w, dw_b);
    gemm_tc<1,false><<<ggrid(L, D, 1), 256>>>(p_convsilu, pw_w, p_outconv, L, D, D, D, D, D,
        0, 0, 0, pw_b, nullptr, nullptr, -1);
    // 15. mix -> x2
    mix_kernel<<<L, 256>>>(x, mem);
    // 16. gate + top2 + column softmax + compaction
    gate_kernel<<<L, 256>>>(norm2_w, gate_w);
    colsoftmax_kernel<<<2, 1024>>>();
    zero_cnt_kernel<<<1, 32>>>();
    compact_kernel<<<(L+255)/256, 256>>>();
    // 17. routed experts — BATCHED over blockIdx.z (early-exit on g_cnt)
    gemm_tc<0,true><<<ggrid(L, 2*HID, E), 256>>>(p_x2, e_w1, p_h1,
        L, 2*HID, D, D, D, 2*HID,
        0, (long long)2*HID*D, (long long)L*2*HID, nullptr, nullptr, nullptr, -2);
    silumul_kernel<<<dim3(L, E), 256>>>();
    gemm_tc<0,false><<<ggrid(L, D, E), 256>>>(p_hh, e_w2, p_y,
        L, D, HID, HID, HID, D,
        (long long)L*HID, (long long)D*HID, (long long)L*D, nullptr, nullptr, nullptr, -2);
    gemm_tc<5,false><<<ggrid(L, D, E), 256>>>(p_y, e_lw, p_y,
        L, D, D, D, D, D,
        (long long)L*D, (long long)D*D, 0, e_lb, nullptr, nullptr, -2);
    // 18. out = x2 + 0.1*moe
    final_kernel<<<L, 256>>>(out);
}

// round 4
// speedup vs baseline: 8.0436x; 1.8073x over previous
#include <cuda_runtime.h>
#include <math.h>

namespace {
constexpr int L   = 1024;
constexpr int D   = 1024;
constexpr int H   = 16;
constexpr int KVH = 8;
constexpr int HD  = 64;
constexpr int NS  = 128;
constexpr int DT  = 64;
constexpr int E   = 8;
constexpr int HID = 4096;
constexpr int PRJ = DT + 2*NS; // 320
constexpr int BK  = 16;
constexpr int NSTG = 4;
constexpr int LDS_ = BK + 4;   // 20 floats: rows stay 16B aligned
}

// ------------------ scratch: device globals ------------------
__device__ float g_xn[L*D];
__device__ float g_sn[L*D];
__device__ float g_snsel[L*D];
__device__ float g_proj[L*PRJ];
__device__ float g_delta[L*D];
__device__ float g_tmpssm[L*D];
__device__ float g_outssm[L*D];
__device__ float g_qlin[L*D];
__device__ float g_klin[L*KVH*HD];
__device__ float g_vlin[L*KVH*HD];
__device__ float g_qr[H*L*HD];
__device__ float g_kr[H*L*HD];
__device__ float g_vt[H*HD*L];
__device__ float g_scores[H*L*L];
__device__ float g_sinv[H*L];
__device__ float g_attnout[L*D];
__device__ float g_outattn[L*D];
__device__ float g_convsilu[L*D];
__device__ float g_outconv[L*D];
__device__ float g_weights[L*4];
__device__ float g_x2[L*D];
__device__ float g_vals[L*2];
__device__ int   g_topidx[L*2];
__device__ float g_w0[L];
__device__ float g_w1[L];
__device__ int   g_cnt[E];
__device__ int   g_tok[E*L];
__device__ int   g_slot[E*L];
__device__ float g_h1[(long long)E*L*2*HID];
__device__ float g_hh[(long long)E*L*HID];
__device__ float g_y [(long long)E*L*D];
__device__ float g_moe[2*L*D];

__device__ __forceinline__ float warpSum(float v){
    #pragma unroll
    for (int o = 16; o; o >>= 1) v += __shfl_xor_sync(0xffffffffu, v, o);
    return v;
}

__device__ __forceinline__ void cp16(float* smem, const float* g, bool pred){
    unsigned s = (unsigned)__cvta_generic_to_shared(smem);
    int sz = pred ? 16 : 0;
    asm volatile("cp.async.cg.shared.global [%0], [%1], 16, %2;\n"
                 :: "r"(s), "l"(g), "r"(sz));
}
__device__ __forceinline__ void cpcommit(){ asm volatile("cp.async.commit_group;\n"); }
template<int N> __device__ __forceinline__ void cpwait(){ asm volatile("cp.async.wait_group %0;\n" :: "n"(N)); }

__device__ __forceinline__ void mma8(float* d, const unsigned* a, const unsigned* b){
    asm volatile(
      "mma.sync.aligned.m16n8k8.row.col.f32.tf32.tf32.f32 "
      "{%0,%1,%2,%3},{%4,%5,%6,%7},{%8,%9},{%0,%1,%2,%3};"
      : "+f"(d[0]), "+f"(d[1]), "+f"(d[2]), "+f"(d[3])
      : "r"(a[0]), "r"(a[1]), "r"(a[2]), "r"(a[3]), "r"(b[0]), "r"(b[1]));
}

// ---- tf32 tensor-core NT GEMM, cp.async 4-stage pipeline ----
// C[m,n] = sum_k A[m,k]*B[n,k]
// EPI: 0 none | 1 +x0[n] | 2 softplus(+x0[n]) | 3 x1[m,n]*sigmoid((+x0[n])*x2p[n])
//      | 5 moe scatter (+x0[e*D+n]) | 6 v*x0[bz*L+m] (attn normalize)
// eidx==-2: e=blockIdx.z, M=g_cnt[e]. GATHER: A row = g_tok[e*L+row].
template<int BM_, int BN_, int WM, int WN, int EPI, bool GATHER>
__global__ void __launch_bounds__(256, 1)
gemm_tc(const float* __restrict__ A, const float* __restrict__ B, float* __restrict__ Cp,
        int M, int N, int K, int lda, int ldb, int ldc,
        long long sA, long long sB, long long sC,
        const float* __restrict__ x0, const float* __restrict__ x1,
        const float* __restrict__ x2p, int eidx)
{
    constexpr int WTM = BM_/WM, WTN = BN_/WN;
    constexpr int MT = WTM/16, NT = WTN/8;
    constexpr int CA = BM_/64, CB = BN_/64;   // 16B chunks per thread
    extern __shared__ float smem[];
    float* Asm = smem;                          // NSTG*BM_*LDS_
    float* Bsm = smem + NSTG*BM_*LDS_;

    int bm = blockIdx.y, bn = blockIdx.x, bz = blockIdx.z;
    int e = eidx;
    if (eidx == -2) e = bz;
    if (e >= 0) M = g_cnt[e];
    int row0 = bm*BM_, col0 = bn*BN_;
    if (row0 >= M) return;
    A += bz*sA; B += bz*sB; Cp += bz*sC;

    int tid = threadIdx.x;
    int lane = tid & 31, warp = tid >> 5;
    int wm = warp / WN, wn = warp % WN;
    int g  = lane >> 2, t4 = lane & 3;

    // loader setup
    const float* aptr[CA]; int adst[CA]; bool avp[CA];
    #pragma unroll
    for (int i = 0; i < CA; i++){
        int ci = tid + i*256;
        int mloc = ci >> 2, blk = ci & 3;
        int gm = row0 + mloc;
        bool v = gm < M;
        long long src = 0;
        if (v) src = GATHER ? (long long)g_tok[e*L + gm] : gm;
        aptr[i] = A + src*lda + blk*4;
        adst[i] = mloc*LDS_ + blk*4;
        avp[i]  = v;
    }
    const float* bptr[CB]; int bdst[CB]; bool bvp[CB];
    #pragma unroll
    for (int i = 0; i < CB; i++){
        int ci = tid + i*256;
        int nloc = ci >> 2, blk = ci & 3;
        int gn = col0 + nloc;
        bool v = gn < N;
        bptr[i] = B + (long long)(v ? gn : 0)*ldb + blk*4;
        bdst[i] = nloc*LDS_ + blk*4;
        bvp[i]  = v;
    }

    int NTILES = K / BK;
    // prologue: stages 0..NSTG-2
    #pragma unroll
    for (int s = 0; s < NSTG-1; s++){
        if (s < NTILES){
            #pragma unroll
            for (int i = 0; i < CA; i++) cp16(&Asm[s*BM_*LDS_ + adst[i]], aptr[i] + s*BK, avp[i]);
            #pragma unroll
            for (int i = 0; i < CB; i++) cp16(&Bsm[s*BN_*LDS_ + bdst[i]], bptr[i] + s*BK, bvp[i]);
        }
        cpcommit();
    }
    cpwait<NSTG-2>();
    __syncthreads();

    float acc[MT][NT][4];
    #pragma unroll
    for (int i = 0; i < MT; i++)
        #pragma unroll
        for (int j = 0; j < NT; j++)
            #pragma unroll
            for (int c = 0; c < 4; c++) acc[i][j][c] = 0.f;

    for (int kt = 0; kt < NTILES; kt++){
        int cur = kt % NSTG;
        int nxt = kt + NSTG - 1;
        if (nxt < NTILES){
            int s = nxt % NSTG;
            #pragma unroll
            for (int i = 0; i < CA; i++) cp16(&Asm[s*BM_*LDS_ + adst[i]], aptr[i] + nxt*BK, avp[i]);
            #pragma unroll
            for (int i = 0; i < CB; i++) cp16(&Bsm[s*BN_*LDS_ + bdst[i]], bptr[i] + nxt*BK, bvp[i]);
        }
        cpcommit();

        const float* Ac = Asm + cur*BM_*LDS_;
        const float* Bc = Bsm + cur*BN_*LDS_;
        #pragma unroll
        for (int kp = 0; kp < 2; kp++){
            int kb = kp*8;
            unsigned a[MT][4], b[NT][2];
            #pragma unroll
            for (int mt = 0; mt < MT; mt++){
                int m = wm*WTM + mt*16 + g;
                a[mt][0] = __float_as_uint(Ac[ m   *LDS_ + kb + t4]);
                a[mt][1] = __float_as_uint(Ac[(m+8)*LDS_ + kb + t4]);
                a[mt][2] = __float_as_uint(Ac[ m   *LDS_ + kb + t4 + 4]);
                a[mt][3] = __float_as_uint(Ac[(m+8)*LDS_ + kb + t4 + 4]);
            }
            #pragma unroll
            for (int nt = 0; nt < NT; nt++){
                int n = wn*WTN + nt*8 + g;
                b[nt][0] = __float_as_uint(Bc[n*LDS_ + kb + t4]);
                b[nt][1] = __float_as_uint(Bc[n*LDS_ + kb + t4 + 4]);
            }
            #pragma unroll
            for (int mt = 0; mt < MT; mt++)
                #pragma unroll
                for (int nt = 0; nt < NT; nt++)
                    mma8(acc[mt][nt], a[mt], b[nt]);
        }
        cpwait<NSTG-2>();
        __syncthreads();
    }

    // epilogue
    int mbase = row0 + wm*WTM, nbase = col0 + wn*WTN;
    #pragma unroll
    for (int mt = 0; mt < MT; mt++){
        #pragma unroll
        for (int nt = 0; nt < NT; nt++){
            #pragma unroll
            for (int c = 0; c < 4; c++){
                int m = mbase + mt*16 + g + (c >= 2 ? 8 : 0);
                int n = nbase + nt*8 + t4*2 + (c & 1);
                if (m >= M || n >= N) continue;
                float v = acc[mt][nt][c];
                if (EPI == 0){
                    Cp[(long long)m*ldc + n] = v;
                } else if (EPI == 1){
                    Cp[(long long)m*ldc + n] = v + x0[n];
                } else if (EPI == 2){
                    float zz = v + x0[n];
                    Cp[(long long)m*ldc + n] = fmaxf(zz, 0.f) + log1pf(__expf(-fabsf(zz)));
                } else if (EPI == 3){
                    float zz = (v + x0[n]) * x2p[n];
                    Cp[(long long)m*ldc + n] = x1[(long long)m*ldc + n] / (1.f + __expf(-zz));
                } else if (EPI == 5){
                    int tok = g_tok[e*L + m];
                    int sl  = g_slot[e*L + m];
                    float w = sl ? g_w1[tok] : g_w0[tok];
                    g_moe[((long long)sl*L + tok)*D + n] = w * (v + x0[(long long)e*D + n]);
                } else if (EPI == 6){
                    Cp[(long long)m*ldc + n] = v * x0[(long long)bz*L + m];
                }
            }
        }
    }
}

// ------------------ elementwise / reduction kernels ------------------
__global__ void rms_kernel(const float* __restrict__ in, const float* __restrict__ w,
                           float* __restrict__ out){
    int t = blockIdx.x;
    const float* row = in + (long long)t*D;
    __shared__ float sred[8];
    __shared__ float sscale;
    float ss = 0.f;
    for (int d = threadIdx.x; d < D; d += 256){ float v = row[d]; ss += v*v; }
    ss = warpSum(ss);
    if ((threadIdx.x & 31) == 0) sred[threadIdx.x >> 5] = ss;
    __syncthreads();
    if (threadIdx.x == 0){
        float s = 0.f;
        #pragma unroll
        for (int i = 0; i < 8; i++) s += sred[i];
        sscale = rsqrtf(s*(1.f/D) + 1e-6f);
    }
    __syncthreads();
    float sc = sscale;
    for (int d = threadIdx.x; d < D; d += 256)
        out[(long long)t*D + d] = row[d]*sc*w[d];
}

__global__ void router_kernel(const float* __restrict__ rw){
    int t = blockIdx.x;
    __shared__ float sm[8][4];
    float acc[4] = {0,0,0,0};
    for (int d = threadIdx.x; d < D; d += 256){
        float xv = g_xn[(long long)t*D + d];
        #pragma unroll
        for (int j = 0; j < 4; j++) acc[j] += xv*rw[j*D + d];
    }
    #pragma unroll
    for (int j = 0; j < 4; j++) acc[j] = warpSum(acc[j]);
    if ((threadIdx.x & 31) == 0){
        #pragma unroll
        for (int j = 0; j < 4; j++) sm[threadIdx.x >> 5][j] = acc[j];
    }
    __syncthreads();
    if (threadIdx.x == 0){
        float lg[4];
        #pragma unroll
        for (int j = 0; j < 4; j++){ float s = 0.f; for (int w2 = 0; w2 < 8; w2++) s += sm[w2][j]; lg[j] = s; }
        float mx = fmaxf(fmaxf(lg[0], lg[1]), fmaxf(lg[2], lg[3]));
        float sum = 0.f;
        #pragma unroll
        for (int j = 0; j < 4; j++){ lg[j] = __expf(lg[j] - mx); sum += lg[j]; }
        const float c[4] = {0.5f, 0.2f, 0.15f, 0.15f};
        float s2 = 0.f;
        #pragma unroll
        for (int j = 0; j < 4; j++){ lg[j] = lg[j]/sum*c[j]; s2 += lg[j]; }
        #pragma unroll
        for (int j = 0; j < 4; j++) g_weights[t*4 + j] = lg[j]/s2;
    }
}

// SSM scan: warp per channel; lane owns states lane*4..lane*4+3; depth-4 prefetch.
__global__ void scan_kernel(const float* __restrict__ A_log, const float* __restrict__ Dp){
    int w = threadIdx.x >> 5, lane = threadIdx.x & 31;
    int d = blockIdx.x*4 + w;
    float4 A0;
    A0.x = -__expf(A_log[d*NS + lane*4 + 0]);
    A0.y = -__expf(A_log[d*NS + lane*4 + 1]);
    A0.z = -__expf(A_log[d*NS + lane*4 + 2]);
    A0.w = -__expf(A_log[d*NS + lane*4 + 3]);
    float Dpd = Dp[d];
    float4 h = make_float4(0.f,0.f,0.f,0.f);
    const float4* __restrict__ P4 = (const float4*)g_proj;   // row stride 80 float4
    float4 b[4], c[4]; float dt[4], xt[4];
    #pragma unroll
    for (int j = 0; j < 4; j++){
        b[j]  = P4[j*80 + 16 + lane];
        c[j]  = P4[j*80 + 48 + lane];
        dt[j] = g_delta[j*D + d];
        xt[j] = g_snsel[j*D + d];
    }
    for (int t0 = 0; t0 < L; t0 += 4){
        #pragma unroll
        for (int j = 0; j < 4; j++){
            int t = t0 + j;
            float4 bb = b[j], cc = c[j];
            float ddt = dt[j], xx = xt[j];
            int tn = t + 4;
            if (tn < L){
                b[j]  = P4[tn*80 + 16 + lane];
                c[j]  = P4[tn*80 + 48 + lane];
                dt[j] = g_delta[tn*D + d];
                xt[j] = g_snsel[tn*D + d];
            }
            float dx = ddt*xx;
            h.x = __expf(ddt*A0.x)*h.x + dx*bb.x;
            h.y = __expf(ddt*A0.y)*h.y + dx*bb.y;
            h.z = __expf(ddt*A0.z)*h.z + dx*bb.z;
            h.w = __expf(ddt*A0.w)*h.w + dx*bb.w;
            float acc = h.x*cc.x + h.y*cc.y + h.z*cc.z + h.w*cc.w;
            acc = warpSum(acc);
            if (lane == 0)
                g_tmpssm[t*D + d] = acc + g_xn[t*D + d]*Dpd;
        }
    }
}

__global__ void qrope_kernel(const float* __restrict__ qn_w){
    int t = blockIdx.x;
    int h = threadIdx.x >> 5, l = threadIdx.x & 31;
    float a = g_qlin[(long long)t*D + h*HD + l];
    float b = g_qlin[(long long)t*D + h*HD + l + 32];
    float ss = warpSum(a*a + b*b);
    float sc = rsqrtf(ss*(1.f/HD) + 1e-6f) * 0.125f;
    a = a*sc*qn_w[l]; b = b*sc*qn_w[l+32];
    float inv = __expf(-(float)l*(1.f/32.f)*9.210340371976184f);
    float s, c; sincosf((float)t*inv, &s, &c);
    long long base = ((long long)h*L + t)*HD;
    g_qr[base + l]      = a*c - b*s;
    g_qr[base + l + 32] = b*c + a*s;
}

__global__ void kvrope_kernel(const float* __restrict__ kn_w){
    int t = blockIdx.x;
    int w = threadIdx.x >> 5, l = threadIdx.x & 31;
    if (w < 8){
        int j = w;
        float a = g_klin[(long long)t*(KVH*HD) + j*HD + l];
        float b = g_klin[(long long)t*(KVH*HD) + j*HD + l + 32];
        float ss = warpSum(a*a + b*b);
        float sc = rsqrtf(ss*(1.f/HD) + 1e-6f);
        a = a*sc*kn_w[l]; b = b*sc*kn_w[l+32];
        float inv = __expf(-(float)l*(1.f/32.f)*9.210340371976184f);
        float s, c; sincosf((float)t*inv, &s, &c);
        float o1 = a*c - b*s;
        float o2 = b*c + a*s;
        #pragma unroll
        for (int r = 0; r < 2; r++){
            long long base = ((long long)(2*j + r)*L + t)*HD;
            g_kr[base + l]      = o1;
            g_kr[base + l + 32] = o2;
        }
    } else {
        int j = w - 8;
        float a = g_vlin[(long long)t*(KVH*HD) + j*HD + l];
        float b = g_vlin[(long long)t*(KVH*HD) + j*HD + l + 32];
        #pragma unroll
        for (int r = 0; r < 2; r++){
            long long hb = (long long)(2*j + r)*HD;
            g_vt[(hb + l)*L + t]      = a;
            g_vt[(hb + l + 32)*L + t] = b;
        }
    }
}

// softmax: leaves rows as unnormalized exp; stores reciprocal sum in g_sinv.
__global__ void softmax_kernel(){
    float* row = g_scores + (long long)blockIdx.x*L;
    __shared__ float sred[8];
    int tid = threadIdx.x;
    float mx = -1e30f;
    for (int i = tid; i < L; i += 256) mx = fmaxf(mx, row[i]);
    #pragma unroll
    for (int o = 16; o; o >>= 1) mx = fmaxf(mx, __shfl_xor_sync(0xffffffffu, mx, o));
    if ((tid & 31) == 0) sred[tid >> 5] = mx;
    __syncthreads();
    if (tid == 0){ float m = sred[0]; for (int i = 1; i < 8; i++) m = fmaxf(m, sred[i]); sred[0] = m; }
    __syncthreads();
    mx = sred[0];
    __syncthreads();
    float s = 0.f;
    for (int i = tid; i < L; i += 256){ float e = __expf(row[i] - mx); row[i] = e; s += e; }
    s = warpSum(s);
    if ((tid & 31) == 0) sred[tid >> 5] = s;
    __syncthreads();
    if (tid == 0){
        float t2 = 0.f;
        for (int i = 0; i < 8; i++) t2 += sred[i];
        g_sinv[blockIdx.x] = 1.f/t2;
    }
}

__global__ void conv_silu_kernel(const float* __restrict__ dww, const float* __restrict__ dwb){
    int t = blockIdx.x;
    for (int d = threadIdx.x; d < D; d += 256){
        float v = g_xn[(long long)t*D + d]*dww[d*3+1] + dwb[d];
        if (t > 0)     v += g_xn[(long long)(t-1)*D + d]*dww[d*3+0];
        if (t < L-1)   v += g_xn[(long long)(t+1)*D + d]*dww[d*3+2];
        g_convsilu[(long long)t*D + d] = v/(1.f + __expf(-v));
    }
}

__global__ void mix_kernel(const float* __restrict__ x, const float* __restrict__ mem){
    int t = blockIdx.x;
    float w0 = g_weights[t*4+0], w1 = g_weights[t*4+1];
    float w2 = g_weights[t*4+2], w3 = g_weights[t*4+3];
    for (int d = threadIdx.x; d < D; d += 256){
        long long i = (long long)t*D + d;
        g_x2[i] = x[i] + w0*g_outssm[i] + w1*g_outattn[i] + w2*g_outconv[i] + w3*mem[i];
    }
}

__global__ void gate_kernel(const float* __restrict__ n2w, const float* __restrict__ gw){
    int t = blockIdx.x;
    __shared__ float sred[8];
    __shared__ float sacc[8][8];
    __shared__ float sscale;
    const float* row = g_x2 + (long long)t*D;
    float ss = 0.f;
    for (int d = threadIdx.x; d < D; d += 256){ float v = row[d]; ss += v*v; }
    ss = warpSum(ss);
    if ((threadIdx.x & 31) == 0) sred[threadIdx.x >> 5] = ss;
    __syncthreads();
    if (threadIdx.x == 0){
        float s = 0.f; for (int i = 0; i < 8; i++) s += sred[i];
        sscale = rsqrtf(s*(1.f/D) + 1e-6f);
    }
    __syncthreads();
    float sc = sscale;
    float acc[8] = {0,0,0,0,0,0,0,0};
    for (int d = threadIdx.x; d < D; d += 256){
        float xv = row[d]*sc*n2w[d];
        #pragma unroll
        for (int e = 0; e < 8; e++) acc[e] += xv*gw[e*D + d];
    }
    #pragma unroll
    for (int e = 0; e < 8; e++) acc[e] = warpSum(acc[e]);
    if ((threadIdx.x & 31) == 0){
        #pragma unroll
        for (int e = 0; e < 8; e++) sacc[threadIdx.x >> 5][e] = acc[e];
    }
    __syncthreads();
    if (threadIdx.x == 0){
        float lg[8];
        #pragma unroll
        for (int e = 0; e < 8; e++){ float s = 0.f; for (int w2 = 0; w2 < 8; w2++) s += sacc[w2][e]; lg[e] = s; }
        float v1 = -1e30f; int i1 = 0;
        for (int e = 0; e < 8; e++) if (lg[e] > v1){ v1 = lg[e]; i1 = e; }
        float v2 = -1e30f; int i2 = 0;
        for (int e = 0; e < 8; e++) if (e != i1 && lg[e] > v2){ v2 = lg[e]; i2 = e; }
        g_vals[t*2+0] = v1; g_vals[t*2+1] = v2;
        g_topidx[t*2+0] = i1; g_topidx[t*2+1] = i2;
    }
}

__global__ void colsoftmax_kernel(){
    int i = blockIdx.x;
    int t = threadIdx.x;
    __shared__ float red[32];
    float v = g_vals[t*2 + i];
    float m = v;
    #pragma unroll
    for (int o = 16; o; o >>= 1) m = fmaxf(m, __shfl_xor_sync(0xffffffffu, m, o));
    if ((t & 31) == 0) red[t >> 5] = m;
    __syncthreads();
    if (t == 0){ float mm = red[0]; for (int k = 1; k < 32; k++) mm = fmaxf(mm, red[k]); red[0] = mm; }
    __syncthreads();
    m = red[0];
    __syncthreads();
    float e = __expf(v - m);
    float s = e;
    #pragma unroll
    for (int o = 16; o; o >>= 1) s += __shfl_xor_sync(0xffffffffu, s, o);
    if ((t & 31) == 0) red[t >> 5] = s;
    __syncthreads();
    if (t == 0){ float sm = 0.f; for (int k = 0; k < 32; k++) sm += red[k]; red[0] = sm; }
    __syncthreads();
    float w = e / red[0];
    if (i == 0) g_w0[t] = w; else g_w1[t] = w;
}

__global__ void zero_cnt_kernel(){
    if (threadIdx.x < E) g_cnt[threadIdx.x] = 0;
}

__global__ void compact_kernel(){
    int t = blockIdx.x*256 + threadIdx.x;
    if (t >= L) return;
    #pragma unroll
    for (int i = 0; i < 2; i++){
        int e = g_topidx[t*2 + i];
        int p = atomicAdd(&g_cnt[e], 1);
        g_tok[e*L + p] = t;
        g_slot[e*L + p] = i;
    }
}

__global__ void silumul_kernel(){
    int e = blockIdx.y, r = blockIdx.x;
    if (r >= g_cnt[e]) return;
    const float* h = g_h1 + ((long long)e*L + r)*2*HID;
    float* o = g_hh + ((long long)e*L + r)*HID;
    for (int c = threadIdx.x; c < HID; c += 256){
        float a = h[c], g = h[HID + c];
        o[c] = a/(1.f + __expf(-a))*g;
    }
}

__global__ void final_kernel(float* __restrict__ out){
    int t = blockIdx.x;
    for (int d = threadIdx.x; d < D; d += 256){
        long long i = (long long)t*D + d;
        out[i] = g_x2[i] + 0.1f*(g_moe[i] + g_moe[(long long)L*D + i]);
    }
}

// ------------------ launch ------------------
namespace {
constexpr int SMEM_BIG   = NSTG*(128+128)*LDS_*4;  // 81920
constexpr int SMEM_SMALL = NSTG*(128+ 64)*LDS_*4;  // 61440
inline dim3 grd(int M, int N, int BN_, int Z){ return dim3((N+BN_-1)/BN_, (M+127)/128, Z); }
}

extern "C" void kernel_launch(void* const* d_in, const int* in_sizes, int n_in,
                              void* d_out, int out_size)
{
    const float* x         = (const float*)d_in[0];
    const float* mem       = (const float*)d_in[1];
    const float* norm1_w   = (const float*)d_in[2];
    const float* router_w  = (const float*)d_in[3];
    const float* ssm_norm_w= (const float*)d_in[4];
    const float* x_proj_w  = (const float*)d_in[5];
    const float* dt_proj_w = (const float*)d_in[6];
    const float* dt_proj_b = (const float*)d_in[7];
    const float* A_log     = (const float*)d_in[8];
    const float* D_param   = (const float*)d_in[9];
    const float* ssm_out_w = (const float*)d_in[10];
    const float* sel_w     = (const float*)d_in[11];
    const float* sel_b     = (const float*)d_in[12];
    const float* sel_gate  = (const float*)d_in[13];
    const float* q_w       = (const float*)d_in[14];
    const float* k_w       = (const float*)d_in[15];
    const float* v_w       = (const float*)d_in[16];
    const float* o_w       = (const float*)d_in[17];
    const float* qn_w      = (const float*)d_in[18];
    const float* kn_w      = (const float*)d_in[19];
    const float* dw_w      = (const float*)d_in[20];
    const float* dw_b      = (const float*)d_in[21];
    const float* pw_w      = (const float*)d_in[22];
    const float* pw_b      = (const float*)d_in[23];
    const float* norm2_w   = (const float*)d_in[24];
    const float* gate_w    = (const float*)d_in[25];
    const float* e_w1      = (const float*)d_in[26];
    const float* e_w2      = (const float*)d_in[27];
    const float* e_lw      = (const float*)d_in[28];
    const float* e_lb      = (const float*)d_in[29];
    float* out = (float*)d_out;

    float *p_xn, *p_sn, *p_snsel, *p_proj, *p_delta, *p_tmpssm, *p_outssm;
    float *p_qlin, *p_klin, *p_vlin, *p_qr, *p_kr, *p_vt, *p_scores, *p_sinv, *p_attnout;
    float *p_outattn, *p_convsilu, *p_outconv, *p_x2, *p_h1, *p_hh, *p_y;
    cudaGetSymbolAddress((void**)&p_xn, g_xn);
    cudaGetSymbolAddress((void**)&p_sn, g_sn);
    cudaGetSymbolAddress((void**)&p_snsel, g_snsel);
    cudaGetSymbolAddress((void**)&p_proj, g_proj);
    cudaGetSymbolAddress((void**)&p_delta, g_delta);
    cudaGetSymbolAddress((void**)&p_tmpssm, g_tmpssm);
    cudaGetSymbolAddress((void**)&p_outssm, g_outssm);
    cudaGetSymbolAddress((void**)&p_qlin, g_qlin);
    cudaGetSymbolAddress((void**)&p_klin, g_klin);
    cudaGetSymbolAddress((void**)&p_vlin, g_vlin);
    cudaGetSymbolAddress((void**)&p_qr, g_qr);
    cudaGetSymbolAddress((void**)&p_kr, g_kr);
    cudaGetSymbolAddress((void**)&p_vt, g_vt);
    cudaGetSymbolAddress((void**)&p_scores, g_scores);
    cudaGetSymbolAddress((void**)&p_sinv, g_sinv);
    cudaGetSymbolAddress((void**)&p_attnout, g_attnout);
    cudaGetSymbolAddress((void**)&p_outattn, g_outattn);
    cudaGetSymbolAddress((void**)&p_convsilu, g_convsilu);
    cudaGetSymbolAddress((void**)&p_outconv, g_outconv);
    cudaGetSymbolAddress((void**)&p_x2, g_x2);
    cudaGetSymbolAddress((void**)&p_h1, g_h1);
    cudaGetSymbolAddress((void**)&p_hh, g_hh);
    cudaGetSymbolAddress((void**)&p_y, g_y);

    // opt into >48KB dynamic smem for every instantiation we use
    #define SETSM(KER, SZ) cudaFuncSetAttribute((const void*)&KER, cudaFuncAttributeMaxDynamicSharedMemorySize, SZ)
    SETSM((gemm_tc<128,64,4,2,3,false>), SMEM_SMALL);
    SETSM((gemm_tc<128,64,4,2,0,false>), SMEM_SMALL);
    SETSM((gemm_tc<128,64,4,2,2,false>), SMEM_SMALL);
    SETSM((gemm_tc<128,64,4,2,1,false>), SMEM_SMALL);
    SETSM((gemm_tc<128,64,4,2,6,false>), SMEM_SMALL);
    SETSM((gemm_tc<128,128,2,4,0,false>), SMEM_BIG);
    SETSM((gemm_tc<128,128,2,4,0,true>),  SMEM_BIG);
    SETSM((gemm_tc<128,128,2,4,5,false>), SMEM_BIG);
    #undef SETSM

    // 1. xn = rms(x); router
    rms_kernel<<<L, 256>>>(x, norm1_w, p_xn);
    router_kernel<<<L, 256>>>(router_w);
    // 2. sn = rms(xn)
    rms_kernel<<<L, 256>>>(p_xn, ssm_norm_w, p_sn);
    // 3. sn_sel
    gemm_tc<128,64,4,2,3,false><<<grd(L, D, 64, 1), 256, SMEM_SMALL>>>(p_sn, sel_w, p_snsel,
        L, D, D, D, D, D, 0, 0, 0, sel_b, p_sn, sel_gate, -1);
    // 4. proj
    gemm_tc<128,64,4,2,0,false><<<grd(L, PRJ, 64, 1), 256, SMEM_SMALL>>>(p_snsel, x_proj_w, p_proj,
        L, PRJ, D, D, D, PRJ, 0, 0, 0, nullptr, nullptr, nullptr, -1);
    // 5. delta
    gemm_tc<128,64,4,2,2,false><<<grd(L, D, 64, 1), 256, SMEM_SMALL>>>(p_proj, dt_proj_w, p_delta,
        L, D, DT, PRJ, DT, D, 0, 0, 0, dt_proj_b, nullptr, nullptr, -1);
    // 6. SSM scan
    scan_kernel<<<D/4, 128>>>(A_log, D_param);
    // 7. out_ssm
    gemm_tc<128,64,4,2,0,false><<<grd(L, D, 64, 1), 256, SMEM_SMALL>>>(p_tmpssm, ssm_out_w, p_outssm,
        L, D, D, D, D, D, 0, 0, 0, nullptr, nullptr, nullptr, -1);
    // 8. q/k/v
    gemm_tc<128,64,4,2,0,false><<<grd(L, D, 64, 1), 256, SMEM_SMALL>>>(p_xn, q_w, p_qlin,
        L, D, D, D, D, D, 0, 0, 0, nullptr, nullptr, nullptr, -1);
    gemm_tc<128,64,4,2,0,false><<<grd(L, KVH*HD, 64, 1), 256, SMEM_SMALL>>>(p_xn, k_w, p_klin,
        L, KVH*HD, D, D, D, KVH*HD, 0, 0, 0, nullptr, nullptr, nullptr, -1);
    gemm_tc<128,64,4,2,0,false><<<grd(L, KVH*HD, 64, 1), 256, SMEM_SMALL>>>(p_xn, v_w, p_vlin,
        L, KVH*HD, D, D, D, KVH*HD, 0, 0, 0, nullptr, nullptr, nullptr, -1);
    // 9. rms+rope
    qrope_kernel<<<L, 512>>>(qn_w);
    kvrope_kernel<<<L, 512>>>(kn_w);
    // 10. scores
    gemm_tc<128,128,2,4,0,false><<<grd(L, L, 128, H), 256, SMEM_BIG>>>(p_qr, p_kr, p_scores,
        L, L, HD, HD, HD, L,
        (long long)L*HD, (long long)L*HD, (long long)L*L, nullptr, nullptr, nullptr, -1);
    // 11. softmax (unnormalized exp + rowsum)
    softmax_kernel<<<H*L, 256>>>();
    // 12. attn@v with epilogue normalization
    gemm_tc<128,64,4,2,6,false><<<grd(L, HD, 64, H), 256, SMEM_SMALL>>>(p_scores, p_vt, p_attnout,
        L, HD, L, L, L, D,
        (long long)L*L, (long long)HD*L, (long long)HD, p_sinv, nullptr, nullptr, -1);
    // 13. out_attn
    gemm_tc<128,64,4,2,0,false><<<grd(L, D, 64, 1), 256, SMEM_SMALL>>>(p_attnout, o_w, p_outattn,
        L, D, D, D, D, D, 0, 0, 0, nullptr, nullptr, nullptr, -1);
    // 14. conv + pointwise
    conv_silu_kernel<<<L, 256>>>(dw_w, dw_b);
    gemm_tc<128,64,4,2,1,false><<<grd(L, D, 64, 1), 256, SMEM_SMALL>>>(p_convsilu, pw_w, p_outconv,
        L, D, D, D, D, D, 0, 0, 0, pw_b, nullptr, nullptr, -1);
    // 15. mix
    mix_kernel<<<L, 256>>>(x, mem);
    // 16. gate + top2 + seq softmax + compaction
    gate_kernel<<<L, 256>>>(norm2_w, gate_w);
    colsoftmax_kernel<<<2, 1024>>>();
    zero_cnt_kernel<<<1, 32>>>();
    compact_kernel<<<(L+255)/256, 256>>>();
    // 17. routed experts, batched over z
    gemm_tc<128,128,2,4,0,true><<<grd(L, 2*HID, 128, E), 256, SMEM_BIG>>>(p_x2, e_w1, p_h1,
        L, 2*HID, D, D, D, 2*HID,
        0, (long long)2*HID*D, (long long)L*2*HID, nullptr, nullptr, nullptr, -2);
    silumul_kernel<<<dim3(L, E), 256>>>();
    gemm_tc<128,128,2,4,0,false><<<grd(L, D, 128, E), 256, SMEM_BIG>>>(p_hh, e_w2, p_y,
        L, D, HID, HID, HID, D,
        (long long)L*HID, (long long)D*HID, (long long)L*D, nullptr, nullptr, nullptr, -2);
    gemm_tc<128,128,2,4,5,false><<<grd(L, D, 128, E), 256, SMEM_BIG>>>(p_y, e_lw, p_y,
        L, D, D, D, D, D,
        (long long)L*D, (long long)D*D, 0, e_lb, nullptr, nullptr, -2);
    // 18. final
    final_kernel<<<L, 256>>>(out);
}

// round 5
// speedup vs baseline: 8.3430x; 1.0372x over previous
#include <cuda_runtime.h>
#include <math.h>

namespace {
constexpr int L   = 1024;
constexpr int D   = 1024;
constexpr int H   = 16;
constexpr int KVH = 8;
constexpr int HD  = 64;
constexpr int NS  = 128;
constexpr int DT  = 64;
constexpr int E   = 8;
constexpr int HID = 4096;
constexpr int PRJ = DT + 2*NS; // 320
constexpr int BK  = 16;
constexpr int NSTG = 3;
constexpr int LDS_ = BK + 4;   // 20 floats: rows stay 16B aligned
}

// ------------------ scratch: device globals ------------------
__device__ float g_xn[L*D];
__device__ float g_sn[L*D];
__device__ float g_snsel[L*D];
__device__ float g_proj[L*PRJ];
__device__ float g_delta[L*D];
__device__ float g_tmpssm[L*D];
__device__ float g_outssm[L*D];
__device__ float g_qlin[L*D];
__device__ float g_klin[L*KVH*HD];
__device__ float g_vlin[L*KVH*HD];
__device__ float g_qr[H*L*HD];
__device__ float g_kr[H*L*HD];
__device__ float g_vt[H*HD*L];
__device__ float g_scores[H*L*L];
__device__ float g_sinv[H*L];
__device__ float g_attnout[L*D];
__device__ float g_outattn[L*D];
__device__ float g_convsilu[L*D];
__device__ float g_outconv[L*D];
__device__ float g_weights[L*4];
__device__ float g_x2[L*D];
__device__ float g_vals[L*2];
__device__ int   g_topidx[L*2];
__device__ float g_w0[L];
__device__ float g_w1[L];
__device__ int   g_cnt[E];
__device__ int   g_tok[E*L];
__device__ int   g_slot[E*L];
__device__ float g_h1[(long long)E*L*2*HID];
__device__ float g_hh[(long long)E*L*HID];
__device__ float g_y [(long long)E*L*D];
__device__ float g_moe[2*L*D];

__device__ __forceinline__ float warpSum(float v){
    #pragma unroll
    for (int o = 16; o; o >>= 1) v += __shfl_xor_sync(0xffffffffu, v, o);
    return v;
}

__device__ __forceinline__ void cp16(float* smem, const float* g, bool pred){
    unsigned s = (unsigned)__cvta_generic_to_shared(smem);
    int sz = pred ? 16 : 0;
    asm volatile("cp.async.cg.shared.global [%0], [%1], 16, %2;\n"
                 :: "r"(s), "l"(g), "r"(sz));
}
__device__ __forceinline__ void cpcommit(){ asm volatile("cp.async.commit_group;\n"); }
template<int N> __device__ __forceinline__ void cpwait(){ asm volatile("cp.async.wait_group %0;\n" :: "n"(N)); }

__device__ __forceinline__ void mma8(float* d, const unsigned* a, const unsigned* b){
    asm volatile(
      "mma.sync.aligned.m16n8k8.row.col.f32.tf32.tf32.f32 "
      "{%0,%1,%2,%3},{%4,%5,%6,%7},{%8,%9},{%0,%1,%2,%3};"
      : "+f"(d[0]), "+f"(d[1]), "+f"(d[2]), "+f"(d[3])
      : "r"(a[0]), "r"(a[1]), "r"(a[2]), "r"(a[3]), "r"(b[0]), "r"(b[1]));
}

// ---- tf32 tensor-core NT GEMM, cp.async 3-stage pipeline, 2 CTAs/SM ----
// C[m,n] = sum_k A[m,k]*B[n,k]
// EPI: 0 none | 1 +x0[n] | 2 softplus(+x0[n]) | 3 x1[m,n]*sigmoid((+x0[n])*x2p[n])
//      | 5 moe scatter (+x0[e*D+n]) | 6 v*x0[bz*L+m] (attn normalize)
// eidx==-2: e=blockIdx.z, M=g_cnt[e]. GATHER: A row = g_tok[e*L+row].
template<int BM_, int BN_, int WM, int WN, int EPI, bool GATHER>
__global__ void __launch_bounds__(256, 2)
gemm_tc(const float* __restrict__ A, const float* __restrict__ B, float* __restrict__ Cp,
        int M, int N, int K, int lda, int ldb, int ldc,
        long long sA, long long sB, long long sC,
        const float* __restrict__ x0, const float* __restrict__ x1,
        const float* __restrict__ x2p, int eidx)
{
    constexpr int WTM = BM_/WM, WTN = BN_/WN;
    constexpr int MT = WTM/16, NT = WTN/8;
    constexpr int CA = BM_/64, CB = BN_/64;   // 16B chunks per thread
    extern __shared__ float smem[];
    float* Asm = smem;                          // NSTG*BM_*LDS_
    float* Bsm = smem + NSTG*BM_*LDS_;

    int bm = blockIdx.y, bn = blockIdx.x, bz = blockIdx.z;
    int e = eidx;
    if (eidx == -2) e = bz;
    if (e >= 0) M = g_cnt[e];
    int row0 = bm*BM_, col0 = bn*BN_;
    if (row0 >= M) return;
    A += bz*sA; B += bz*sB; Cp += bz*sC;

    int tid = threadIdx.x;
    int lane = tid & 31, warp = tid >> 5;
    int wm = warp / WN, wn = warp % WN;
    int g  = lane >> 2, t4 = lane & 3;

    // loader setup
    const float* aptr[CA]; int adst[CA]; bool avp[CA];
    #pragma unroll
    for (int i = 0; i < CA; i++){
        int ci = tid + i*256;
        int mloc = ci >> 2, blk = ci & 3;
        int gm = row0 + mloc;
        bool v = gm < M;
        long long src = 0;
        if (v) src = GATHER ? (long long)g_tok[e*L + gm] : gm;
        aptr[i] = A + src*lda + blk*4;
        adst[i] = mloc*LDS_ + blk*4;
        avp[i]  = v;
    }
    const float* bptr[CB]; int bdst[CB]; bool bvp[CB];
    #pragma unroll
    for (int i = 0; i < CB; i++){
        int ci = tid + i*256;
        int nloc = ci >> 2, blk = ci & 3;
        int gn = col0 + nloc;
        bool v = gn < N;
        bptr[i] = B + (long long)(v ? gn : 0)*ldb + blk*4;
        bdst[i] = nloc*LDS_ + blk*4;
        bvp[i]  = v;
    }

    int NTILES = K / BK;
    // prologue: stages 0..NSTG-2
    #pragma unroll
    for (int s = 0; s < NSTG-1; s++){
        if (s < NTILES){
            #pragma unroll
            for (int i = 0; i < CA; i++) cp16(&Asm[s*BM_*LDS_ + adst[i]], aptr[i] + s*BK, avp[i]);
            #pragma unroll
            for (int i = 0; i < CB; i++) cp16(&Bsm[s*BN_*LDS_ + bdst[i]], bptr[i] + s*BK, bvp[i]);
        }
        cpcommit();
    }
    cpwait<NSTG-2>();
    __syncthreads();

    float acc[MT][NT][4];
    #pragma unroll
    for (int i = 0; i < MT; i++)
        #pragma unroll
        for (int j = 0; j < NT; j++)
            #pragma unroll
            for (int c = 0; c < 4; c++) acc[i][j][c] = 0.f;

    for (int kt = 0; kt < NTILES; kt++){
        int cur = kt % NSTG;
        int nxt = kt + NSTG - 1;
        if (nxt < NTILES){
            int s = nxt % NSTG;
            #pragma unroll
            for (int i = 0; i < CA; i++) cp16(&Asm[s*BM_*LDS_ + adst[i]], aptr[i] + nxt*BK, avp[i]);
            #pragma unroll
            for (int i = 0; i < CB; i++) cp16(&Bsm[s*BN_*LDS_ + bdst[i]], bptr[i] + nxt*BK, bvp[i]);
        }
        cpcommit();

        const float* Ac = Asm + cur*BM_*LDS_;
        const float* Bc = Bsm + cur*BN_*LDS_;
        #pragma unroll
        for (int kp = 0; kp < 2; kp++){
            int kb = kp*8;
            unsigned a[MT][4], b[NT][2];
            #pragma unroll
            for (int mt = 0; mt < MT; mt++){
                int m = wm*WTM + mt*16 + g;
                a[mt][0] = __float_as_uint(Ac[ m   *LDS_ + kb + t4]);
                a[mt][1] = __float_as_uint(Ac[(m+8)*LDS_ + kb + t4]);
                a[mt][2] = __float_as_uint(Ac[ m   *LDS_ + kb + t4 + 4]);
                a[mt][3] = __float_as_uint(Ac[(m+8)*LDS_ + kb + t4 + 4]);
            }
            #pragma unroll
            for (int nt = 0; nt < NT; nt++){
                int n = wn*WTN + nt*8 + g;
                b[nt][0] = __float_as_uint(Bc[n*LDS_ + kb + t4]);
                b[nt][1] = __float_as_uint(Bc[n*LDS_ + kb + t4 + 4]);
            }
            #pragma unroll
            for (int mt = 0; mt < MT; mt++)
                #pragma unroll
                for (int nt = 0; nt < NT; nt++)
                    mma8(acc[mt][nt], a[mt], b[nt]);
        }
        cpwait<NSTG-2>();
        __syncthreads();
    }

    // epilogue
    int mbase = row0 + wm*WTM, nbase = col0 + wn*WTN;
    #pragma unroll
    for (int mt = 0; mt < MT; mt++){
        #pragma unroll
        for (int nt = 0; nt < NT; nt++){
            #pragma unroll
            for (int c = 0; c < 4; c++){
                int m = mbase + mt*16 + g + (c >= 2 ? 8 : 0);
                int n = nbase + nt*8 + t4*2 + (c & 1);
                if (m >= M || n >= N) continue;
                float v = acc[mt][nt][c];
                if (EPI == 0){
                    Cp[(long long)m*ldc + n] = v;
                } else if (EPI == 1){
                    Cp[(long long)m*ldc + n] = v + x0[n];
                } else if (EPI == 2){
                    float zz = v + x0[n];
                    Cp[(long long)m*ldc + n] = fmaxf(zz, 0.f) + log1pf(__expf(-fabsf(zz)));
                } else if (EPI == 3){
                    float zz = (v + x0[n]) * x2p[n];
                    Cp[(long long)m*ldc + n] = x1[(long long)m*ldc + n] / (1.f + __expf(-zz));
                } else if (EPI == 5){
                    int tok = g_tok[e*L + m];
                    int sl  = g_slot[e*L + m];
                    float w = sl ? g_w1[tok] : g_w0[tok];
                    g_moe[((long long)sl*L + tok)*D + n] = w * (v + x0[(long long)e*D + n]);
                } else if (EPI == 6){
                    Cp[(long long)m*ldc + n] = v * x0[(long long)bz*L + m];
                }
            }
        }
    }
}

// ------------------ elementwise / reduction kernels ------------------
__global__ void rms_kernel(const float* __restrict__ in, const float* __restrict__ w,
                           float* __restrict__ out){
    int t = blockIdx.x;
    const float* row = in + (long long)t*D;
    __shared__ float sred[8];
    __shared__ float sscale;
    float ss = 0.f;
    for (int d = threadIdx.x; d < D; d += 256){ float v = row[d]; ss += v*v; }
    ss = warpSum(ss);
    if ((threadIdx.x & 31) == 0) sred[threadIdx.x >> 5] = ss;
    __syncthreads();
    if (threadIdx.x == 0){
        float s = 0.f;
        #pragma unroll
        for (int i = 0; i < 8; i++) s += sred[i];
        sscale = rsqrtf(s*(1.f/D) + 1e-6f);
    }
    __syncthreads();
    float sc = sscale;
    for (int d = threadIdx.x; d < D; d += 256)
        out[(long long)t*D + d] = row[d]*sc*w[d];
}

__global__ void router_kernel(const float* __restrict__ rw){
    int t = blockIdx.x;
    __shared__ float sm[8][4];
    float acc[4] = {0,0,0,0};
    for (int d = threadIdx.x; d < D; d += 256){
        float xv = g_xn[(long long)t*D + d];
        #pragma unroll
        for (int j = 0; j < 4; j++) acc[j] += xv*rw[j*D + d];
    }
    #pragma unroll
    for (int j = 0; j < 4; j++) acc[j] = warpSum(acc[j]);
    if ((threadIdx.x & 31) == 0){
        #pragma unroll
        for (int j = 0; j < 4; j++) sm[threadIdx.x >> 5][j] = acc[j];
    }
    __syncthreads();
    if (threadIdx.x == 0){
        float lg[4];
        #pragma unroll
        for (int j = 0; j < 4; j++){ float s = 0.f; for (int w2 = 0; w2 < 8; w2++) s += sm[w2][j]; lg[j] = s; }
        float mx = fmaxf(fmaxf(lg[0], lg[1]), fmaxf(lg[2], lg[3]));
        float sum = 0.f;
        #pragma unroll
        for (int j = 0; j < 4; j++){ lg[j] = __expf(lg[j] - mx); sum += lg[j]; }
        const float c[4] = {0.5f, 0.2f, 0.15f, 0.15f};
        float s2 = 0.f;
        #pragma unroll
        for (int j = 0; j < 4; j++){ lg[j] = lg[j]/sum*c[j]; s2 += lg[j]; }
        #pragma unroll
        for (int j = 0; j < 4; j++) g_weights[t*4 + j] = lg[j]/s2;
    }
}

// SSM scan: warp per channel; lane owns states lane*4..lane*4+3; depth-4 prefetch.
__global__ void scan_kernel(const float* __restrict__ A_log, const float* __restrict__ Dp){
    int w = threadIdx.x >> 5, lane = threadIdx.x & 31;
    int d = blockIdx.x*4 + w;
    float4 A0;
    A0.x = -__expf(A_log[d*NS + lane*4 + 0]);
    A0.y = -__expf(A_log[d*NS + lane*4 + 1]);
    A0.z = -__expf(A_log[d*NS + lane*4 + 2]);
    A0.w = -__expf(A_log[d*NS + lane*4 + 3]);
    float Dpd = Dp[d];
    float4 h = make_float4(0.f,0.f,0.f,0.f);
    const float4* __restrict__ P4 = (const float4*)g_proj;   // row stride 80 float4
    float4 b[4], c[4]; float dt[4], xt[4];
    #pragma unroll
    for (int j = 0; j < 4; j++){
        b[j]  = P4[j*80 + 16 + lane];
        c[j]  = P4[j*80 + 48 + lane];
        dt[j] = g_delta[j*D + d];
        xt[j] = g_snsel[j*D + d];
    }
    for (int t0 = 0; t0 < L; t0 += 4){
        #pragma unroll
        for (int j = 0; j < 4; j++){
            int t = t0 + j;
            float4 bb = b[j], cc = c[j];
            float ddt = dt[j], xx = xt[j];
            int tn = t + 4;
            if (tn < L){
                b[j]  = P4[tn*80 + 16 + lane];
                c[j]  = P4[tn*80 + 48 + lane];
                dt[j] = g_delta[tn*D + d];
                xt[j] = g_snsel[tn*D + d];
            }
            float dx = ddt*xx;
            h.x = __expf(ddt*A0.x)*h.x + dx*bb.x;
            h.y = __expf(ddt*A0.y)*h.y + dx*bb.y;
            h.z = __expf(ddt*A0.z)*h.z + dx*bb.z;
            h.w = __expf(ddt*A0.w)*h.w + dx*bb.w;
            float acc = h.x*cc.x + h.y*cc.y + h.z*cc.z + h.w*cc.w;
            acc = warpSum(acc);
            if (lane == 0)
                g_tmpssm[t*D + d] = acc + g_xn[t*D + d]*Dpd;
        }
    }
}

__global__ void qrope_kernel(const float* __restrict__ qn_w){
    int t = blockIdx.x;
    int h = threadIdx.x >> 5, l = threadIdx.x & 31;
    float a = g_qlin[(long long)t*D + h*HD + l];
    float b = g_qlin[(long long)t*D + h*HD + l + 32];
    float ss = warpSum(a*a + b*b);
    float sc = rsqrtf(ss*(1.f/HD) + 1e-6f) * 0.125f;
    a = a*sc*qn_w[l]; b = b*sc*qn_w[l+32];
    float inv = __expf(-(float)l*(1.f/32.f)*9.210340371976184f);
    float s, c; sincosf((float)t*inv, &s, &c);
    long long base = ((long long)h*L + t)*HD;
    g_qr[base + l]      = a*c - b*s;
    g_qr[base + l + 32] = b*c + a*s;
}

__global__ void kvrope_kernel(const float* __restrict__ kn_w){
    int t = blockIdx.x;
    int w = threadIdx.x >> 5, l = threadIdx.x & 31;
    if (w < 8){
        int j = w;
        float a = g_klin[(long long)t*(KVH*HD) + j*HD + l];
        float b = g_klin[(long long)t*(KVH*HD) + j*HD + l + 32];
        float ss = warpSum(a*a + b*b);
        float sc = rsqrtf(ss*(1.f/HD) + 1e-6f);
        a = a*sc*kn_w[l]; b = b*sc*kn_w[l+32];
        float inv = __expf(-(float)l*(1.f/32.f)*9.210340371976184f);
        float s, c; sincosf((float)t*inv, &s, &c);
        float o1 = a*c - b*s;
        float o2 = b*c + a*s;
        #pragma unroll
        for (int r = 0; r < 2; r++){
            long long base = ((long long)(2*j + r)*L + t)*HD;
            g_kr[base + l]      = o1;
            g_kr[base + l + 32] = o2;
        }
    } else {
        int j = w - 8;
        float a = g_vlin[(long long)t*(KVH*HD) + j*HD + l];
        float b = g_vlin[(long long)t*(KVH*HD) + j*HD + l + 32];
        #pragma unroll
        for (int r = 0; r < 2; r++){
            long long hb = (long long)(2*j + r)*HD;
            g_vt[(hb + l)*L + t]      = a;
            g_vt[(hb + l + 32)*L + t] = b;
        }
    }
}

// softmax: leaves rows as unnormalized exp; stores reciprocal sum in g_sinv.
__global__ void softmax_kernel(){
    float* row = g_scores + (long long)blockIdx.x*L;
    __shared__ float sred[8];
    int tid = threadIdx.x;
    float mx = -1e30f;
    for (int i = tid; i < L; i += 256) mx = fmaxf(mx, row[i]);
    #pragma unroll
    for (int o = 16; o; o >>= 1) mx = fmaxf(mx, __shfl_xor_sync(0xffffffffu, mx, o));
    if ((tid & 31) == 0) sred[tid >> 5] = mx;
    __syncthreads();
    if (tid == 0){ float m = sred[0]; for (int i = 1; i < 8; i++) m = fmaxf(m, sred[i]); sred[0] = m; }
    __syncthreads();
    mx = sred[0];
    __syncthreads();
    float s = 0.f;
    for (int i = tid; i < L; i += 256){ float e = __expf(row[i] - mx); row[i] = e; s += e; }
    s = warpSum(s);
    if ((tid & 31) == 0) sred[tid >> 5] = s;
    __syncthreads();
    if (tid == 0){
        float t2 = 0.f;
        for (int i = 0; i < 8; i++) t2 += sred[i];
        g_sinv[blockIdx.x] = 1.f/t2;
    }
}

__global__ void conv_silu_kernel(const float* __restrict__ dww, const float* __restrict__ dwb){
    int t = blockIdx.x;
    for (int d = threadIdx.x; d < D; d += 256){
        float v = g_xn[(long long)t*D + d]*dww[d*3+1] + dwb[d];
        if (t > 0)     v += g_xn[(long long)(t-1)*D + d]*dww[d*3+0];
        if (t < L-1)   v += g_xn[(long long)(t+1)*D + d]*dww[d*3+2];
        g_convsilu[(long long)t*D + d] = v/(1.f + __expf(-v));
    }
}

__global__ void mix_kernel(const float* __restrict__ x, const float* __restrict__ mem){
    int t = blockIdx.x;
    float w0 = g_weights[t*4+0], w1 = g_weights[t*4+1];
    float w2 = g_weights[t*4+2], w3 = g_weights[t*4+3];
    for (int d = threadIdx.x; d < D; d += 256){
        long long i = (long long)t*D + d;
        g_x2[i] = x[i] + w0*g_outssm[i] + w1*g_outattn[i] + w2*g_outconv[i] + w3*mem[i];
    }
}

__global__ void gate_kernel(const float* __restrict__ n2w, const float* __restrict__ gw){
    int t = blockIdx.x;
    __shared__ float sred[8];
    __shared__ float sacc[8][8];
    __shared__ float sscale;
    const float* row = g_x2 + (long long)t*D;
    float ss = 0.f;
    for (int d = threadIdx.x; d < D; d += 256){ float v = row[d]; ss += v*v; }
    ss = warpSum(ss);
    if ((threadIdx.x & 31) == 0) sred[threadIdx.x >> 5] = ss;
    __syncthreads();
    if (threadIdx.x == 0){
        float s = 0.f; for (int i = 0; i < 8; i++) s += sred[i];
        sscale = rsqrtf(s*(1.f/D) + 1e-6f);
    }
    __syncthreads();
    float sc = sscale;
    float acc[8] = {0,0,0,0,0,0,0,0};
    for (int d = threadIdx.x; d < D; d += 256){
        float xv = row[d]*sc*n2w[d];
        #pragma unroll
        for (int e = 0; e < 8; e++) acc[e] += xv*gw[e*D + d];
    }
    #pragma unroll
    for (int e = 0; e < 8; e++) acc[e] = warpSum(acc[e]);
    if ((threadIdx.x & 31) == 0){
        #pragma unroll
        for (int e = 0; e < 8; e++) sacc[threadIdx.x >> 5][e] = acc[e];
    }
    __syncthreads();
    if (threadIdx.x == 0){
        float lg[8];
        #pragma unroll
        for (int e = 0; e < 8; e++){ float s = 0.f; for (int w2 = 0; w2 < 8; w2++) s += sacc[w2][e]; lg[e] = s; }
        float v1 = -1e30f; int i1 = 0;
        for (int e = 0; e < 8; e++) if (lg[e] > v1){ v1 = lg[e]; i1 = e; }
        float v2 = -1e30f; int i2 = 0;
        for (int e = 0; e < 8; e++) if (e != i1 && lg[e] > v2){ v2 = lg[e]; i2 = e; }
        g_vals[t*2+0] = v1; g_vals[t*2+1] = v2;
        g_topidx[t*2+0] = i1; g_topidx[t*2+1] = i2;
    }
}

__global__ void colsoftmax_kernel(){
    int i = blockIdx.x;
    int t = threadIdx.x;
    __shared__ float red[32];
    float v = g_vals[t*2 + i];
    float m = v;
    #pragma unroll
    for (int o = 16; o; o >>= 1) m = fmaxf(m, __shfl_xor_sync(0xffffffffu, m, o));
    if ((t & 31) == 0) red[t >> 5] = m;
    __syncthreads();
    if (t == 0){ float mm = red[0]; for (int k = 1; k < 32; k++) mm = fmaxf(mm, red[k]); red[0] = mm; }
    __syncthreads();
    m = red[0];
    __syncthreads();
    float e = __expf(v - m);
    float s = e;
    #pragma unroll
    for (int o = 16; o; o >>= 1) s += __shfl_xor_sync(0xffffffffu, s, o);
    if ((t & 31) == 0) red[t >> 5] = s;
    __syncthreads();
    if (t == 0){ float sm = 0.f; for (int k = 0; k < 32; k++) sm += red[k]; red[0] = sm; }
    __syncthreads();
    float w = e / red[0];
    if (i == 0) g_w0[t] = w; else g_w1[t] = w;
}

__global__ void zero_cnt_kernel(){
    if (threadIdx.x < E) g_cnt[threadIdx.x] = 0;
}

__global__ void compact_kernel(){
    int t = blockIdx.x*256 + threadIdx.x;
    if (t >= L) return;
    #pragma unroll
    for (int i = 0; i < 2; i++){
        int e = g_topidx[t*2 + i];
        int p = atomicAdd(&g_cnt[e], 1);
        g_tok[e*L + p] = t;
        g_slot[e*L + p] = i;
    }
}

__global__ void silumul_kernel(){
    int e = blockIdx.y, r = blockIdx.x;
    if (r >= g_cnt[e]) return;
    const float* h = g_h1 + ((long long)e*L + r)*2*HID;
    float* o = g_hh + ((long long)e*L + r)*HID;
    for (int c = threadIdx.x; c < HID; c += 256){
        float a = h[c], g = h[HID + c];
        o[c] = a/(1.f + __expf(-a))*g;
    }
}

__global__ void final_kernel(float* __restrict__ out){
    int t = blockIdx.x;
    for (int d = threadIdx.x; d < D; d += 256){
        long long i = (long long)t*D + d;
        out[i] = g_x2[i] + 0.1f*(g_moe[i] + g_moe[(long long)L*D + i]);
    }
}

// ------------------ launch ------------------
namespace {
constexpr int SMEM_BIG   = NSTG*(128+128)*LDS_*4;  // 61440
constexpr int SMEM_SMALL = NSTG*(128+ 64)*LDS_*4;  // 46080
inline dim3 grd(int M, int N, int BN_, int Z){ return dim3((N+BN_-1)/BN_, (M+127)/128, Z); }
}

extern "C" void kernel_launch(void* const* d_in, const int* in_sizes, int n_in,
                              void* d_out, int out_size)
{
    const float* x         = (const float*)d_in[0];
    const float* mem       = (const float*)d_in[1];
    const float* norm1_w   = (const float*)d_in[2];
    const float* router_w  = (const float*)d_in[3];
    const float* ssm_norm_w= (const float*)d_in[4];
    const float* x_proj_w  = (const float*)d_in[5];
    const float* dt_proj_w = (const float*)d_in[6];
    const float* dt_proj_b = (const float*)d_in[7];
    const float* A_log     = (const float*)d_in[8];
    const float* D_param   = (const float*)d_in[9];
    const float* ssm_out_w = (const float*)d_in[10];
    const float* sel_w     = (const float*)d_in[11];
    const float* sel_b     = (const float*)d_in[12];
    const float* sel_gate  = (const float*)d_in[13];
    const float* q_w       = (const float*)d_in[14];
    const float* k_w       = (const float*)d_in[15];
    const float* v_w       = (const float*)d_in[16];
    const float* o_w       = (const float*)d_in[17];
    const float* qn_w      = (const float*)d_in[18];
    const float* kn_w      = (const float*)d_in[19];
    const float* dw_w      = (const float*)d_in[20];
    const float* dw_b      = (const float*)d_in[21];
    const float* pw_w      = (const float*)d_in[22];
    const float* pw_b      = (const float*)d_in[23];
    const float* norm2_w   = (const float*)d_in[24];
    const float* gate_w    = (const float*)d_in[25];
    const float* e_w1      = (const float*)d_in[26];
    const float* e_w2      = (const float*)d_in[27];
    const float* e_lw      = (const float*)d_in[28];
    const float* e_lb      = (const float*)d_in[29];
    float* out = (float*)d_out;

    float *p_xn, *p_sn, *p_snsel, *p_proj, *p_delta, *p_tmpssm, *p_outssm;
    float *p_qlin, *p_klin, *p_vlin, *p_qr, *p_kr, *p_vt, *p_scores, *p_sinv, *p_attnout;
    float *p_outattn, *p_convsilu, *p_outconv, *p_x2, *p_h1, *p_hh, *p_y;
    cudaGetSymbolAddress((void**)&p_xn, g_xn);
    cudaGetSymbolAddress((void**)&p_sn, g_sn);
    cudaGetSymbolAddress((void**)&p_snsel, g_snsel);
    cudaGetSymbolAddress((void**)&p_proj, g_proj);
    cudaGetSymbolAddress((void**)&p_delta, g_delta);
    cudaGetSymbolAddress((void**)&p_tmpssm, g_tmpssm);
    cudaGetSymbolAddress((void**)&p_outssm, g_outssm);
    cudaGetSymbolAddress((void**)&p_qlin, g_qlin);
    cudaGetSymbolAddress((void**)&p_klin, g_klin);
    cudaGetSymbolAddress((void**)&p_vlin, g_vlin);
    cudaGetSymbolAddress((void**)&p_qr, g_qr);
    cudaGetSymbolAddress((void**)&p_kr, g_kr);
    cudaGetSymbolAddress((void**)&p_vt, g_vt);
    cudaGetSymbolAddress((void**)&p_scores, g_scores);
    cudaGetSymbolAddress((void**)&p_sinv, g_sinv);
    cudaGetSymbolAddress((void**)&p_attnout, g_attnout);
    cudaGetSymbolAddress((void**)&p_outattn, g_outattn);
    cudaGetSymbolAddress((void**)&p_convsilu, g_convsilu);
    cudaGetSymbolAddress((void**)&p_outconv, g_outconv);
    cudaGetSymbolAddress((void**)&p_x2, g_x2);
    cudaGetSymbolAddress((void**)&p_h1, g_h1);
    cudaGetSymbolAddress((void**)&p_hh, g_hh);
    cudaGetSymbolAddress((void**)&p_y, g_y);

    #define SETSM(KER, SZ) cudaFuncSetAttribute((const void*)&KER, cudaFuncAttributeMaxDynamicSharedMemorySize, SZ)
    SETSM((gemm_tc<128,64,4,2,3,false>), SMEM_SMALL);
    SETSM((gemm_tc<128,64,4,2,0,false>), SMEM_SMALL);
    SETSM((gemm_tc<128,64,4,2,2,false>), SMEM_SMALL);
    SETSM((gemm_tc<128,64,4,2,1,false>), SMEM_SMALL);
    SETSM((gemm_tc<128,64,4,2,6,false>), SMEM_SMALL);
    SETSM((gemm_tc<128,128,2,4,0,false>), SMEM_BIG);
    SETSM((gemm_tc<128,128,2,4,0,true>),  SMEM_BIG);
    SETSM((gemm_tc<128,128,2,4,5,false>), SMEM_BIG);
    #undef SETSM

    // 1. xn = rms(x); router
    rms_kernel<<<L, 256>>>(x, norm1_w, p_xn);
    router_kernel<<<L, 256>>>(router_w);
    // 2. sn = rms(xn)
    rms_kernel<<<L, 256>>>(p_xn, ssm_norm_w, p_sn);
    // 3. sn_sel
    gemm_tc<128,64,4,2,3,false><<<grd(L, D, 64, 1), 256, SMEM_SMALL>>>(p_sn, sel_w, p_snsel,
        L, D, D, D, D, D, 0, 0, 0, sel_b, p_sn, sel_gate, -1);
    // 4. proj
    gemm_tc<128,64,4,2,0,false><<<grd(L, PRJ, 64, 1), 256, SMEM_SMALL>>>(p_snsel, x_proj_w, p_proj,
        L, PRJ, D, D, D, PRJ, 0, 0, 0, nullptr, nullptr, nullptr, -1);
    // 5. delta
    gemm_tc<128,64,4,2,2,false><<<grd(L, D, 64, 1), 256, SMEM_SMALL>>>(p_proj, dt_proj_w, p_delta,
        L, D, DT, PRJ, DT, D, 0, 0, 0, dt_proj_b, nullptr, nullptr, -1);
    // 6. SSM scan
    scan_kernel<<<D/4, 128>>>(A_log, D_param);
    // 7. out_ssm
    gemm_tc<128,64,4,2,0,false><<<grd(L, D, 64, 1), 256, SMEM_SMALL>>>(p_tmpssm, ssm_out_w, p_outssm,
        L, D, D, D, D, D, 0, 0, 0, nullptr, nullptr, nullptr, -1);
    // 8. q/k/v
    gemm_tc<128,64,4,2,0,false><<<grd(L, D, 64, 1), 256, SMEM_SMALL>>>(p_xn, q_w, p_qlin,
        L, D, D, D, D, D, 0, 0, 0, nullptr, nullptr, nullptr, -1);
    gemm_tc<128,64,4,2,0,false><<<grd(L, KVH*HD, 64, 1), 256, SMEM_SMALL>>>(p_xn, k_w, p_klin,
        L, KVH*HD, D, D, D, KVH*HD, 0, 0, 0, nullptr, nullptr, nullptr, -1);
    gemm_tc<128,64,4,2,0,false><<<grd(L, KVH*HD, 64, 1), 256, SMEM_SMALL>>>(p_xn, v_w, p_vlin,
        L, KVH*HD, D, D, D, KVH*HD, 0, 0, 0, nullptr, nullptr, nullptr, -1);
    // 9. rms+rope
    qrope_kernel<<<L, 512>>>(qn_w);
    kvrope_kernel<<<L, 512>>>(kn_w);
    // 10. scores
    gemm_tc<128,128,2,4,0,false><<<grd(L, L, 128, H), 256, SMEM_BIG>>>(p_qr, p_kr, p_scores,
        L, L, HD, HD, HD, L,
        (long long)L*HD, (long long)L*HD, (long long)L*L, nullptr, nullptr, nullptr, -1);
    // 11. softmax (unnormalized exp + rowsum)
    softmax_kernel<<<H*L, 256>>>();
    // 12. attn@v with epilogue normalization
    gemm_tc<128,64,4,2,6,false><<<grd(L, HD, 64, H), 256, SMEM_SMALL>>>(p_scores, p_vt, p_attnout,
        L, HD, L, L, L, D,
        (long long)L*L, (long long)HD*L, (long long)HD, p_sinv, nullptr, nullptr, -1);
    // 13. out_attn
    gemm_tc<128,64,4,2,0,false><<<grd(L, D, 64, 1), 256, SMEM_SMALL>>>(p_attnout, o_w, p_outattn,
        L, D, D, D, D, D, 0, 0, 0, nullptr, nullptr, nullptr, -1);
    // 14. conv + pointwise
    conv_silu_kernel<<<L, 256>>>(dw_w, dw_b);
    gemm_tc<128,64,4,2,1,false><<<grd(L, D, 64, 1), 256, SMEM_SMALL>>>(p_convsilu, pw_w, p_outconv,
        L, D, D, D, D, D, 0, 0, 0, pw_b, nullptr, nullptr, -1);
    // 15. mix
    mix_kernel<<<L, 256>>>(x, mem);
    // 16. gate + top2 + seq softmax + compaction
    gate_kernel<<<L, 256>>>(norm2_w, gate_w);
    colsoftmax_kernel<<<2, 1024>>>();
    zero_cnt_kernel<<<1, 32>>>();
    compact_kernel<<<(L+255)/256, 256>>>();
    // 17. routed experts, batched over z
    gemm_tc<128,128,2,4,0,true><<<grd(L, 2*HID, 128, E), 256, SMEM_BIG>>>(p_x2, e_w1, p_h1,
        L, 2*HID, D, D, D, 2*HID,
        0, (long long)2*HID*D, (long long)L*2*HID, nullptr, nullptr, nullptr, -2);
    silumul_kernel<<<dim3(L, E), 256>>>();
    gemm_tc<128,128,2,4,0,false><<<grd(L, D, 128, E), 256, SMEM_BIG>>>(p_hh, e_w2, p_y,
        L, D, HID, HID, HID, D,
        (long long)L*HID, (long long)D*HID, (long long)L*D, nullptr, nullptr, nullptr, -2);
    gemm_tc<128,128,2,4,5,false><<<grd(L, D, 128, E), 256, SMEM_BIG>>>(p_y, e_lw, p_y,
        L, D, D, D, D, D,
        (long long)L*D, (long long)D*D, 0, e_lb, nullptr, nullptr, -2);
    // 18. final
    final_kernel<<<L, 256>>>(out);
}

// round 6
// speedup vs baseline: 8.4516x; 1.0130x over previous
#include <cuda_runtime.h>
#include <math.h>

namespace {
constexpr int L   = 1024;
constexpr int D   = 1024;
constexpr int H   = 16;
constexpr int KVH = 8;
constexpr int HD  = 64;
constexpr int NS  = 128;
constexpr int DT  = 64;
constexpr int E   = 8;
constexpr int HID = 4096;
constexpr int PRJ = DT + 2*NS; // 320
constexpr int BK  = 16;
constexpr int NSTG = 5;
constexpr int LDS_ = BK + 4;   // 20 floats
constexpr int QKVN = 2048;     // fused q|k|v output width
}

// ------------------ scratch: device globals ------------------
__device__ float g_xn[L*D];
__device__ float g_sn[L*D];
__device__ float g_snsel[L*D];
__device__ float g_proj[L*PRJ];
__device__ float g_delta[L*D];
__device__ float g_tmpssm[L*D];
__device__ float g_outssm[L*D];
__device__ float g_wqkv[QKVN*D];
__device__ float g_qkv[L*QKVN];
__device__ float g_qr[H*L*HD];
__device__ float g_kr[H*L*HD];
__device__ float g_vt[H*HD*L];
__device__ float g_scores[H*L*L];
__device__ float g_sinv[H*L];
__device__ float g_attnout[L*D];
__device__ float g_outattn[L*D];
__device__ float g_convsilu[L*D];
__device__ float g_outconv[L*D];
__device__ float g_weights[L*4];
__device__ float g_x2[L*D];
__device__ float g_vals[L*2];
__device__ int   g_topidx[L*2];
__device__ float g_w0[L];
__device__ float g_w1[L];
__device__ int   g_cnt[E];
__device__ int   g_tok[E*L];
__device__ int   g_slot[E*L];
__device__ float g_h1[(long long)E*L*2*HID];
__device__ float g_hh[(long long)E*L*HID];
__device__ float g_y [(long long)E*L*D];
__device__ float g_moe[2*L*D];

__device__ __forceinline__ float warpSum(float v){
    #pragma unroll
    for (int o = 16; o; o >>= 1) v += __shfl_xor_sync(0xffffffffu, v, o);
    return v;
}

__device__ __forceinline__ void cp16(float* smem, const float* g, bool pred){
    unsigned s = (unsigned)__cvta_generic_to_shared(smem);
    int sz = pred ? 16 : 0;
    asm volatile("cp.async.cg.shared.global [%0], [%1], 16, %2;\n"
                 :: "r"(s), "l"(g), "r"(sz));
}
__device__ __forceinline__ void cpcommit(){ asm volatile("cp.async.commit_group;\n"); }
template<int N> __device__ __forceinline__ void cpwait(){ asm volatile("cp.async.wait_group %0;\n" :: "n"(N)); }

__device__ __forceinline__ void mma8(float* d, const unsigned* a, const unsigned* b){
    asm volatile(
      "mma.sync.aligned.m16n8k8.row.col.f32.tf32.tf32.f32 "
      "{%0,%1,%2,%3},{%4,%5,%6,%7},{%8,%9},{%0,%1,%2,%3};"
      : "+f"(d[0]), "+f"(d[1]), "+f"(d[2]), "+f"(d[3])
      : "r"(a[0]), "r"(a[1]), "r"(a[2]), "r"(a[3]), "r"(b[0]), "r"(b[1]));
}

// ---- tf32 NT GEMM: 5-stage cp.async pipeline + register fragment double-buffer ----
// C[m,n] = sum_k A[m,k]*B[n,k]
// EPI: 0 none | 1 +x0[n] | 2 softplus(+x0[n]) | 3 x1[m,n]*sigmoid((+x0[n])*x2p[n])
//      | 5 moe scatter (+x0[e*D+n]) | 6 v*x0[bz*L+m]
template<int BM_, int BN_, int WM, int WN, int EPI, bool GATHER>
__global__ void __launch_bounds__(256)
gemm_tc(const float* __restrict__ A, const float* __restrict__ B, float* __restrict__ Cp,
        int M, int N, int K, int lda, int ldb, int ldc,
        long long sA, long long sB, long long sC,
        const float* __restrict__ x0, const float* __restrict__ x1,
        const float* __restrict__ x2p, int eidx)
{
    constexpr int WTM = BM_/WM, WTN = BN_/WN;
    constexpr int MT = WTM/16, NT = WTN/8;
    constexpr int CA = BM_/64, CB = BN_/64;
    extern __shared__ float smem[];
    float* Asm = smem;
    float* Bsm = smem + NSTG*BM_*LDS_;

    int bm = blockIdx.y, bn = blockIdx.x, bz = blockIdx.z;
    int e = eidx;
    if (eidx == -2) e = bz;
    if (e >= 0) M = g_cnt[e];
    int row0 = bm*BM_, col0 = bn*BN_;
    if (row0 >= M) return;
    A += bz*sA; B += bz*sB; Cp += bz*sC;

    int tid = threadIdx.x;
    int lane = tid & 31, warp = tid >> 5;
    int wm = warp / WN, wn = warp % WN;
    int g  = lane >> 2, t4 = lane & 3;

    const float* aptr[CA]; int adst[CA]; bool avp[CA];
    #pragma unroll
    for (int i = 0; i < CA; i++){
        int ci = tid + i*256;
        int mloc = ci >> 2, blk = ci & 3;
        int gm = row0 + mloc;
        bool v = gm < M;
        long long src = 0;
        if (v) src = GATHER ? (long long)g_tok[e*L + gm] : gm;
        aptr[i] = A + src*lda + blk*4;
        adst[i] = mloc*LDS_ + blk*4;
        avp[i]  = v;
    }
    const float* bptr[CB]; int bdst[CB]; bool bvp[CB];
    #pragma unroll
    for (int i = 0; i < CB; i++){
        int ci = tid + i*256;
        int nloc = ci >> 2, blk = ci & 3;
        int gn = col0 + nloc;
        bool v = gn < N;
        bptr[i] = B + (long long)(v ? gn : 0)*ldb + blk*4;
        bdst[i] = nloc*LDS_ + blk*4;
        bvp[i]  = v;
    }

    int NTILES = K / BK;
    #pragma unroll
    for (int s = 0; s < NSTG-1; s++){
        if (s < NTILES){
            #pragma unroll
            for (int i = 0; i < CA; i++) cp16(&Asm[s*BM_*LDS_ + adst[i]], aptr[i] + s*BK, avp[i]);
            #pragma unroll
            for (int i = 0; i < CB; i++) cp16(&Bsm[s*BN_*LDS_ + bdst[i]], bptr[i] + s*BK, bvp[i]);
        }
        cpcommit();
    }
    cpwait<NSTG-3>();   // stages 0,1 complete
    __syncthreads();

    float acc[MT][NT][4];
    #pragma unroll
    for (int i = 0; i < MT; i++)
        #pragma unroll
        for (int j = 0; j < NT; j++)
            #pragma unroll
            for (int c = 0; c < 4; c++) acc[i][j][c] = 0.f;

    unsigned af[2][MT][4], bf[2][NT][2];

    #define LOAD_FRAGS(S, KB, BUF) do {                                        \
        const float* Ac_ = Asm + (S)*BM_*LDS_;                                 \
        const float* Bc_ = Bsm + (S)*BN_*LDS_;                                 \
        _Pragma("unroll")                                                      \
        for (int mt = 0; mt < MT; mt++){                                       \
            int m_ = wm*WTM + mt*16 + g;                                       \
            af[BUF][mt][0] = __float_as_uint(Ac_[ m_   *LDS_ + (KB) + t4]);    \
            af[BUF][mt][1] = __float_as_uint(Ac_[(m_+8)*LDS_ + (KB) + t4]);    \
            af[BUF][mt][2] = __float_as_uint(Ac_[ m_   *LDS_ + (KB) + t4+4]);  \
            af[BUF][mt][3] = __float_as_uint(Ac_[(m_+8)*LDS_ + (KB) + t4+4]);  \
        }                                                                      \
        _Pragma("unroll")                                                      \
        for (int nt = 0; nt < NT; nt++){                                       \
            int n_ = wn*WTN + nt*8 + g;                                        \
            bf[BUF][nt][0] = __float_as_uint(Bc_[n_*LDS_ + (KB) + t4]);        \
            bf[BUF][nt][1] = __float_as_uint(Bc_[n_*LDS_ + (KB) + t4+4]);      \
        }                                                                      \
    } while(0)

    #define MMA_ALL(BUF) do {                                                  \
        _Pragma("unroll")                                                      \
        for (int mt = 0; mt < MT; mt++)                                        \
            _Pragma("unroll")                                                  \
            for (int nt = 0; nt < NT; nt++)                                    \
                mma8(acc[mt][nt], af[BUF][mt], bf[BUF][nt]);                   \
    } while(0)

    LOAD_FRAGS(0, 0, 0);

    for (int kt = 0; kt < NTILES; kt++){
        int cur = kt % NSTG;
        int nxt = kt + NSTG - 1;
        if (nxt < NTILES){
            int s = nxt % NSTG;
            #pragma unroll
            for (int i = 0; i < CA; i++) cp16(&Asm[s*BM_*LDS_ + adst[i]], aptr[i] + nxt*BK, avp[i]);
            #pragma unroll
            for (int i = 0; i < CB; i++) cp16(&Bsm[s*BN_*LDS_ + bdst[i]], bptr[i] + nxt*BK, bvp[i]);
        }
        cpcommit();

        // kphase 0: prefetch kphase1 frags, then mma buf0
        LOAD_FRAGS(cur, 8, 1);
        MMA_ALL(0);
        // kphase 1: prefetch next ktile's kphase0 frags (stage kt+1 is complete), mma buf1
        int nk = (kt + 1 < NTILES) ? (kt + 1) : kt;
        LOAD_FRAGS(nk % NSTG, 0, 0);
        MMA_ALL(1);

        cpwait<NSTG-3>();   // stage kt+2 complete before next iter reads kt+1.. (and kt+1 already)
        __syncthreads();
    }
    #undef LOAD_FRAGS
    #undef MMA_ALL

    int mbase = row0 + wm*WTM, nbase = col0 + wn*WTN;
    #pragma unroll
    for (int mt = 0; mt < MT; mt++){
        #pragma unroll
        for (int nt = 0; nt < NT; nt++){
            #pragma unroll
            for (int c = 0; c < 4; c++){
                int m = mbase + mt*16 + g + (c >= 2 ? 8 : 0);
                int n = nbase + nt*8 + t4*2 + (c & 1);
                if (m >= M || n >= N) continue;
                float v = acc[mt][nt][c];
                if (EPI == 0){
                    Cp[(long long)m*ldc + n] = v;
                } else if (EPI == 1){
                    Cp[(long long)m*ldc + n] = v + x0[n];
                } else if (EPI == 2){
                    float zz = v + x0[n];
                    Cp[(long long)m*ldc + n] = fmaxf(zz, 0.f) + log1pf(__expf(-fabsf(zz)));
                } else if (EPI == 3){
                    float zz = (v + x0[n]) * x2p[n];
                    Cp[(long long)m*ldc + n] = x1[(long long)m*ldc + n] / (1.f + __expf(-zz));
                } else if (EPI == 5){
                    int tok = g_tok[e*L + m];
                    int sl  = g_slot[e*L + m];
                    float w = sl ? g_w1[tok] : g_w0[tok];
                    g_moe[((long long)sl*L + tok)*D + n] = w * (v + x0[(long long)e*D + n]);
                } else if (EPI == 6){
                    Cp[(long long)m*ldc + n] = v * x0[(long long)bz*L + m];
                }
            }
        }
    }
}

// ------------------ elementwise / reduction kernels ------------------
__global__ void packqkv_kernel(const float* __restrict__ qw, const float* __restrict__ kw,
                               const float* __restrict__ vw){
    int r = blockIdx.x;
    const float* src = (r < 1024) ? (qw + (long long)r*D)
                     : (r < 1536) ? (kw + (long long)(r-1024)*D)
                                  : (vw + (long long)(r-1536)*D);
    float4* d = (float4*)(g_wqkv + (long long)r*D);
    const float4* s = (const float4*)src;
    for (int c = threadIdx.x; c < D/4; c += 256) d[c] = s[c];
}

__global__ void rms_kernel(const float* __restrict__ in, const float* __restrict__ w,
                           float* __restrict__ out){
    int t = blockIdx.x;
    const float* row = in + (long long)t*D;
    __shared__ float sred[8];
    __shared__ float sscale;
    float ss = 0.f;
    for (int d = threadIdx.x; d < D; d += 256){ float v = row[d]; ss += v*v; }
    ss = warpSum(ss);
    if ((threadIdx.x & 31) == 0) sred[threadIdx.x >> 5] = ss;
    __syncthreads();
    if (threadIdx.x == 0){
        float s = 0.f;
        #pragma unroll
        for (int i = 0; i < 8; i++) s += sred[i];
        sscale = rsqrtf(s*(1.f/D) + 1e-6f);
    }
    __syncthreads();
    float sc = sscale;
    for (int d = threadIdx.x; d < D; d += 256)
        out[(long long)t*D + d] = row[d]*sc*w[d];
}

__global__ void router_kernel(const float* __restrict__ rw){
    int t = blockIdx.x;
    __shared__ float sm[8][4];
    float acc[4] = {0,0,0,0};
    for (int d = threadIdx.x; d < D; d += 256){
        float xv = g_xn[(long long)t*D + d];
        #pragma unroll
        for (int j = 0; j < 4; j++) acc[j] += xv*rw[j*D + d];
    }
    #pragma unroll
    for (int j = 0; j < 4; j++) acc[j] = warpSum(acc[j]);
    if ((threadIdx.x & 31) == 0){
        #pragma unroll
        for (int j = 0; j < 4; j++) sm[threadIdx.x >> 5][j] = acc[j];
    }
    __syncthreads();
    if (threadIdx.x == 0){
        float lg[4];
        #pragma unroll
        for (int j = 0; j < 4; j++){ float s = 0.f; for (int w2 = 0; w2 < 8; w2++) s += sm[w2][j]; lg[j] = s; }
        float mx = fmaxf(fmaxf(lg[0], lg[1]), fmaxf(lg[2], lg[3]));
        float sum = 0.f;
        #pragma unroll
        for (int j = 0; j < 4; j++){ lg[j] = __expf(lg[j] - mx); sum += lg[j]; }
        const float c[4] = {0.5f, 0.2f, 0.15f, 0.15f};
        float s2 = 0.f;
        #pragma unroll
        for (int j = 0; j < 4; j++){ lg[j] = lg[j]/sum*c[j]; s2 += lg[j]; }
        #pragma unroll
        for (int j = 0; j < 4; j++) g_weights[t*4 + j] = lg[j]/s2;
    }
}

__global__ void scan_kernel(const float* __restrict__ A_log, const float* __restrict__ Dp){
    int w = threadIdx.x >> 5, lane = threadIdx.x & 31;
    int d = blockIdx.x*4 + w;
    float4 A0;
    A0.x = -__expf(A_log[d*NS + lane*4 + 0]);
    A0.y = -__expf(A_log[d*NS + lane*4 + 1]);
    A0.z = -__expf(A_log[d*NS + lane*4 + 2]);
    A0.w = -__expf(A_log[d*NS + lane*4 + 3]);
    float Dpd = Dp[d];
    float4 h = make_float4(0.f,0.f,0.f,0.f);
    const float4* __restrict__ P4 = (const float4*)g_proj;
    float4 b[4], c[4]; float dt[4], xt[4];
    #pragma unroll
    for (int j = 0; j < 4; j++){
        b[j]  = P4[j*80 + 16 + lane];
        c[j]  = P4[j*80 + 48 + lane];
        dt[j] = g_delta[j*D + d];
        xt[j] = g_snsel[j*D + d];
    }
    for (int t0 = 0; t0 < L; t0 += 4){
        #pragma unroll
        for (int j = 0; j < 4; j++){
            int t = t0 + j;
            float4 bb = b[j], cc = c[j];
            float ddt = dt[j], xx = xt[j];
            int tn = t + 4;
            if (tn < L){
                b[j]  = P4[tn*80 + 16 + lane];
                c[j]  = P4[tn*80 + 48 + lane];
                dt[j] = g_delta[tn*D + d];
                xt[j] = g_snsel[tn*D + d];
            }
            float dx = ddt*xx;
            h.x = __expf(ddt*A0.x)*h.x + dx*bb.x;
            h.y = __expf(ddt*A0.y)*h.y + dx*bb.y;
            h.z = __expf(ddt*A0.z)*h.z + dx*bb.z;
            h.w = __expf(ddt*A0.w)*h.w + dx*bb.w;
            float acc = h.x*cc.x + h.y*cc.y + h.z*cc.z + h.w*cc.w;
            acc = warpSum(acc);
            if (lane == 0)
                g_tmpssm[t*D + d] = acc + g_xn[t*D + d]*Dpd;
        }
    }
}

// q at cols [0,1024), k at [1024,1536), v at [1536,2048) of g_qkv (row stride QKVN)
__global__ void qrope_kernel(const float* __restrict__ qn_w){
    int t = blockIdx.x;
    int h = threadIdx.x >> 5, l = threadIdx.x & 31;
    float a = g_qkv[(long long)t*QKVN + h*HD + l];
    float b = g_qkv[(long long)t*QKVN + h*HD + l + 32];
    float ss = warpSum(a*a + b*b);
    float sc = rsqrtf(ss*(1.f/HD) + 1e-6f) * 0.125f;
    a = a*sc*qn_w[l]; b = b*sc*qn_w[l+32];
    float inv = __expf(-(float)l*(1.f/32.f)*9.210340371976184f);
    float s, c; sincosf((float)t*inv, &s, &c);
    long long base = ((long long)h*L + t)*HD;
    g_qr[base + l]      = a*c - b*s;
    g_qr[base + l + 32] = b*c + a*s;
}

__global__ void kvrope_kernel(const float* __restrict__ kn_w){
    int t = blockIdx.x;
    int w = threadIdx.x >> 5, l = threadIdx.x & 31;
    if (w < 8){
        int j = w;
        float a = g_qkv[(long long)t*QKVN + 1024 + j*HD + l];
        float b = g_qkv[(long long)t*QKVN + 1024 + j*HD + l + 32];
        float ss = warpSum(a*a + b*b);
        float sc = rsqrtf(ss*(1.f/HD) + 1e-6f);
        a = a*sc*kn_w[l]; b = b*sc*kn_w[l+32];
        float inv = __expf(-(float)l*(1.f/32.f)*9.210340371976184f);
        float s, c; sincosf((float)t*inv, &s, &c);
        float o1 = a*c - b*s;
        float o2 = b*c + a*s;
        #pragma unroll
        for (int r = 0; r < 2; r++){
            long long base = ((long long)(2*j + r)*L + t)*HD;
            g_kr[base + l]      = o1;
            g_kr[base + l + 32] = o2;
        }
    } else {
        int j = w - 8;
        float a = g_qkv[(long long)t*QKVN + 1536 + j*HD + l];
        float b = g_qkv[(long long)t*QKVN + 1536 + j*HD + l + 32];
        #pragma unroll
        for (int r = 0; r < 2; r++){
            long long hb = (long long)(2*j + r)*HD;
            g_vt[(hb + l)*L + t]      = a;
            g_vt[(hb + l + 32)*L + t] = b;
        }
    }
}

__global__ void softmax_kernel(){
    float* row = g_scores + (long long)blockIdx.x*L;
    __shared__ float sred[8];
    int tid = threadIdx.x;
    float mx = -1e30f;
    for (int i = tid; i < L; i += 256) mx = fmaxf(mx, row[i]);
    #pragma unroll
    for (int o = 16; o; o >>= 1) mx = fmaxf(mx, __shfl_xor_sync(0xffffffffu, mx, o));
    if ((tid & 31) == 0) sred[tid >> 5] = mx;
    __syncthreads();
    if (tid == 0){ float m = sred[0]; for (int i = 1; i < 8; i++) m = fmaxf(m, sred[i]); sred[0] = m; }
    __syncthreads();
    mx = sred[0];
    __syncthreads();
    float s = 0.f;
    for (int i = tid; i < L; i += 256){ float e = __expf(row[i] - mx); row[i] = e; s += e; }
    s = warpSum(s);
    if ((tid & 31) == 0) sred[tid >> 5] = s;
    __syncthreads();
    if (tid == 0){
        float t2 = 0.f;
        for (int i = 0; i < 8; i++) t2 += sred[i];
        g_sinv[blockIdx.x] = 1.f/t2;
    }
}

__global__ void conv_silu_kernel(const float* __restrict__ dww, const float* __restrict__ dwb){
    int t = blockIdx.x;
    for (int d = threadIdx.x; d < D; d += 256){
        float v = g_xn[(long long)t*D + d]*dww[d*3+1] + dwb[d];
        if (t > 0)     v += g_xn[(long long)(t-1)*D + d]*dww[d*3+0];
        if (t < L-1)   v += g_xn[(long long)(t+1)*D + d]*dww[d*3+2];
        g_convsilu[(long long)t*D + d] = v/(1.f + __expf(-v));
    }
}

__global__ void mix_kernel(const float* __restrict__ x, const float* __restrict__ mem){
    int t = blockIdx.x;
    float w0 = g_weights[t*4+0], w1 = g_weights[t*4+1];
    float w2 = g_weights[t*4+2], w3 = g_weights[t*4+3];
    for (int d = threadIdx.x; d < D; d += 256){
        long long i = (long long)t*D + d;
        g_x2[i] = x[i] + w0*g_outssm[i] + w1*g_outattn[i] + w2*g_outconv[i] + w3*mem[i];
    }
}

__global__ void gate_kernel(const float* __restrict__ n2w, const float* __restrict__ gw){
    int t = blockIdx.x;
    __shared__ float sred[8];
    __shared__ float sacc[8][8];
    __shared__ float sscale;
    const float* row = g_x2 + (long long)t*D;
    float ss = 0.f;
    for (int d = threadIdx.x; d < D; d += 256){ float v = row[d]; ss += v*v; }
    ss = warpSum(ss);
    if ((threadIdx.x & 31) == 0) sred[threadIdx.x >> 5] = ss;
    __syncthreads();
    if (threadIdx.x == 0){
        float s = 0.f; for (int i = 0; i < 8; i++) s += sred[i];
        sscale = rsqrtf(s*(1.f/D) + 1e-6f);
    }
    __syncthreads();
    float sc = sscale;
    float acc[8] = {0,0,0,0,0,0,0,0};
    for (int d = threadIdx.x; d < D; d += 256){
        float xv = row[d]*sc*n2w[d];
        #pragma unroll
        for (int e = 0; e < 8; e++) acc[e] += xv*gw[e*D + d];
    }
    #pragma unroll
    for (int e = 0; e < 8; e++) acc[e] = warpSum(acc[e]);
    if ((threadIdx.x & 31) == 0){
        #pragma unroll
        for (int e = 0; e < 8; e++) sacc[threadIdx.x >> 5][e] = acc[e];
    }
    __syncthreads();
    if (threadIdx.x == 0){
        float lg[8];
        #pragma unroll
        for (int e = 0; e < 8; e++){ float s = 0.f; for (int w2 = 0; w2 < 8; w2++) s += sacc[w2][e]; lg[e] = s; }
        float v1 = -1e30f; int i1 = 0;
        for (int e = 0; e < 8; e++) if (lg[e] > v1){ v1 = lg[e]; i1 = e; }
        float v2 = -1e30f; int i2 = 0;
        for (int e = 0; e < 8; e++) if (e != i1 && lg[e] > v2){ v2 = lg[e]; i2 = e; }
        g_vals[t*2+0] = v1; g_vals[t*2+1] = v2;
        g_topidx[t*2+0] = i1; g_topidx[t*2+1] = i2;
    }
}

__global__ void colsoftmax_kernel(){
    int i = blockIdx.x;
    int t = threadIdx.x;
    __shared__ float red[32];
    float v = g_vals[t*2 + i];
    float m = v;
    #pragma unroll
    for (int o = 16; o; o >>= 1) m = fmaxf(m, __shfl_xor_sync(0xffffffffu, m, o));
    if ((t & 31) == 0) red[t >> 5] = m;
    __syncthreads();
    if (t == 0){ float mm = red[0]; for (int k = 1; k < 32; k++) mm = fmaxf(mm, red[k]); red[0] = mm; }
    __syncthreads();
    m = red[0];
    __syncthreads();
    float e = __expf(v - m);
    float s = e;
    #pragma unroll
    for (int o = 16; o; o >>= 1) s += __shfl_xor_sync(0xffffffffu, s, o);
    if ((t & 31) == 0) red[t >> 5] = s;
    __syncthreads();
    if (t == 0){ float sm = 0.f; for (int k = 0; k < 32; k++) sm += red[k]; red[0] = sm; }
    __syncthreads();
    float w = e / red[0];
    if (i == 0) g_w0[t] = w; else g_w1[t] = w;
}

__global__ void zero_cnt_kernel(){
    if (threadIdx.x < E) g_cnt[threadIdx.x] = 0;
}

__global__ void compact_kernel(){
    int t = blockIdx.x*256 + threadIdx.x;
    if (t >= L) return;
    #pragma unroll
    for (int i = 0; i < 2; i++){
        int e = g_topidx[t*2 + i];
        int p = atomicAdd(&g_cnt[e], 1);
        g_tok[e*L + p] = t;
        g_slot[e*L + p] = i;
    }
}

__global__ void silumul_kernel(){
    int e = blockIdx.y, r = blockIdx.x;
    if (r >= g_cnt[e]) return;
    const float* h = g_h1 + ((long long)e*L + r)*2*HID;
    float* o = g_hh + ((long long)e*L + r)*HID;
    for (int c = threadIdx.x; c < HID; c += 256){
        float a = h[c], g = h[HID + c];
        o[c] = a/(1.f + __expf(-a))*g;
    }
}

__global__ void final_kernel(float* __restrict__ out){
    int t = blockIdx.x;
    for (int d = threadIdx.x; d < D; d += 256){
        long long i = (long long)t*D + d;
        out[i] = g_x2[i] + 0.1f*(g_moe[i] + g_moe[(long long)L*D + i]);
    }
}

// ------------------ launch ------------------
namespace {
constexpr int SMEM_BIG   = NSTG*(128+128)*LDS_*4;  // 102400
constexpr int SMEM_SMALL = NSTG*(128+ 64)*LDS_*4;  // 76800
inline dim3 grd(int M, int N, int BN_, int Z){ return dim3((N+BN_-1)/BN_, (M+127)/128, Z); }
}

extern "C" void kernel_launch(void* const* d_in, const int* in_sizes, int n_in,
                              void* d_out, int out_size)
{
    const float* x         = (const float*)d_in[0];
    const float* mem       = (const float*)d_in[1];
    const float* norm1_w   = (const float*)d_in[2];
    const float* router_w  = (const float*)d_in[3];
    const float* ssm_norm_w= (const float*)d_in[4];
    const float* x_proj_w  = (const float*)d_in[5];
    const float* dt_proj_w = (const float*)d_in[6];
    const float* dt_proj_b = (const float*)d_in[7];
    const float* A_log     = (const float*)d_in[8];
    const float* D_param   = (const float*)d_in[9];
    const float* ssm_out_w = (const float*)d_in[10];
    const float* sel_w     = (const float*)d_in[11];
    const float* sel_b     = (const float*)d_in[12];
    const float* sel_gate  = (const float*)d_in[13];
    const float* q_w       = (const float*)d_in[14];
    const float* k_w       = (const float*)d_in[15];
    const float* v_w       = (const float*)d_in[16];
    const float* o_w       = (const float*)d_in[17];
    const float* qn_w      = (const float*)d_in[18];
    const float* kn_w      = (const float*)d_in[19];
    const float* dw_w      = (const float*)d_in[20];
    const float* dw_b      = (const float*)d_in[21];
    const float* pw_w      = (const float*)d_in[22];
    const float* pw_b      = (const float*)d_in[23];
    const float* norm2_w   = (const float*)d_in[24];
    const float* gate_w    = (const float*)d_in[25];
    const float* e_w1      = (const float*)d_in[26];
    const float* e_w2      = (const float*)d_in[27];
    const float* e_lw      = (const float*)d_in[28];
    const float* e_lb      = (const float*)d_in[29];
    float* out = (float*)d_out;

    float *p_xn, *p_sn, *p_snsel, *p_proj, *p_delta, *p_tmpssm, *p_outssm;
    float *p_wqkv, *p_qkv, *p_qr, *p_kr, *p_vt, *p_scores, *p_sinv, *p_attnout;
    float *p_outattn, *p_convsilu, *p_outconv, *p_x2, *p_h1, *p_hh, *p_y;
    cudaGetSymbolAddress((void**)&p_xn, g_xn);
    cudaGetSymbolAddress((void**)&p_sn, g_sn);
    cudaGetSymbolAddress((void**)&p_snsel, g_snsel);
    cudaGetSymbolAddress((void**)&p_proj, g_proj);
    cudaGetSymbolAddress((void**)&p_delta, g_delta);
    cudaGetSymbolAddress((void**)&p_tmpssm, g_tmpssm);
    cudaGetSymbolAddress((void**)&p_outssm, g_outssm);
    cudaGetSymbolAddress((void**)&p_wqkv, g_wqkv);
    cudaGetSymbolAddress((void**)&p_qkv, g_qkv);
    cudaGetSymbolAddress((void**)&p_qr, g_qr);
    cudaGetSymbolAddress((void**)&p_kr, g_kr);
    cudaGetSymbolAddress((void**)&p_vt, g_vt);
    cudaGetSymbolAddress((void**)&p_scores, g_scores);
    cudaGetSymbolAddress((void**)&p_sinv, g_sinv);
    cudaGetSymbolAddress((void**)&p_attnout, g_attnout);
    cudaGetSymbolAddress((void**)&p_outattn, g_outattn);
    cudaGetSymbolAddress((void**)&p_convsilu, g_convsilu);
    cudaGetSymbolAddress((void**)&p_outconv, g_outconv);
    cudaGetSymbolAddress((void**)&p_x2, g_x2);
    cudaGetSymbolAddress((void**)&p_h1, g_h1);
    cudaGetSymbolAddress((void**)&p_hh, g_hh);
    cudaGetSymbolAddress((void**)&p_y, g_y);

    #define SETSM(KER, SZ) cudaFuncSetAttribute((const void*)&KER, cudaFuncAttributeMaxDynamicSharedMemorySize, SZ)
    SETSM((gemm_tc<128,64,4,2,3,false>), SMEM_SMALL);
    SETSM((gemm_tc<128,64,4,2,0,false>), SMEM_SMALL);
    SETSM((gemm_tc<128,64,4,2,2,false>), SMEM_SMALL);
    SETSM((gemm_tc<128,64,4,2,1,false>), SMEM_SMALL);
    SETSM((gemm_tc<128,64,4,2,6,false>), SMEM_SMALL);
    SETSM((gemm_tc<128,128,2,4,0,false>), SMEM_BIG);
    SETSM((gemm_tc<128,128,2,4,0,true>),  SMEM_BIG);
    SETSM((gemm_tc<128,128,2,4,5,false>), SMEM_BIG);
    #undef SETSM

    // 1. xn = rms(x); router; pack qkv weights
    rms_kernel<<<L, 256>>>(x, norm1_w, p_xn);
    packqkv_kernel<<<QKVN, 256>>>(q_w, k_w, v_w);
    router_kernel<<<L, 256>>>(router_w);
    // 2. sn = rms(xn)
    rms_kernel<<<L, 256>>>(p_xn, ssm_norm_w, p_sn);
    // 3. sn_sel
    gemm_tc<128,64,4,2,3,false><<<grd(L, D, 64, 1), 256, SMEM_SMALL>>>(p_sn, sel_w, p_snsel,
        L, D, D, D, D, D, 0, 0, 0, sel_b, p_sn, sel_gate, -1);
    // 4. proj
    gemm_tc<128,64,4,2,0,false><<<grd(L, PRJ, 64, 1), 256, SMEM_SMALL>>>(p_snsel, x_proj_w, p_proj,
        L, PRJ, D, D, D, PRJ, 0, 0, 0, nullptr, nullptr, nullptr, -1);
    // 5. delta
    gemm_tc<128,64,4,2,2,false><<<grd(L, D, 64, 1), 256, SMEM_SMALL>>>(p_proj, dt_proj_w, p_delta,
        L, D, DT, PRJ, DT, D, 0, 0, 0, dt_proj_b, nullptr, nullptr, -1);
    // 6. SSM scan
    scan_kernel<<<D/4, 128>>>(A_log, D_param);
    // 7. out_ssm
    gemm_tc<128,64,4,2,0,false><<<grd(L, D, 64, 1), 256, SMEM_SMALL>>>(p_tmpssm, ssm_out_w, p_outssm,
        L, D, D, D, D, D, 0, 0, 0, nullptr, nullptr, nullptr, -1);
    // 8. fused qkv
    gemm_tc<128,64,4,2,0,false><<<grd(L, QKVN, 64, 1), 256, SMEM_SMALL>>>(p_xn, p_wqkv, p_qkv,
        L, QKVN, D, D, D, QKVN, 0, 0, 0, nullptr, nullptr, nullptr, -1);
    // 9. rms+rope
    qrope_kernel<<<L, 512>>>(qn_w);
    kvrope_kernel<<<L, 512>>>(kn_w);
    // 10. scores
    gemm_tc<128,128,2,4,0,false><<<grd(L, L, 128, H), 256, SMEM_BIG>>>(p_qr, p_kr, p_scores,
        L, L, HD, HD, HD, L,
        (long long)L*HD, (long long)L*HD, (long long)L*L, nullptr, nullptr, nullptr, -1);
    // 11. softmax
    softmax_kernel<<<H*L, 256>>>();
    // 12. attn@v normalized in epilogue
    gemm_tc<128,64,4,2,6,false><<<grd(L, HD, 64, H), 256, SMEM_SMALL>>>(p_scores, p_vt, p_attnout,
        L, HD, L, L, L, D,
        (long long)L*L, (long long)HD*L, (long long)HD, p_sinv, nullptr, nullptr, -1);
    // 13. out_attn
    gemm_tc<128,64,4,2,0,false><<<grd(L, D, 64, 1), 256, SMEM_SMALL>>>(p_attnout, o_w, p_outattn,
        L, D, D, D, D, D, 0, 0, 0, nullptr, nullptr, nullptr, -1);
    // 14. conv + pointwise
    conv_silu_kernel<<<L, 256>>>(dw_w, dw_b);
    gemm_tc<128,64,4,2,1,false><<<grd(L, D, 64, 1), 256, SMEM_SMALL>>>(p_convsilu, pw_w, p_outconv,
        L, D, D, D, D, D, 0, 0, 0, pw_b, nullptr, nullptr, -1);
    // 15. mix
    mix_kernel<<<L, 256>>>(x, mem);
    // 16. gate + top2 + seq softmax + compaction
    gate_kernel<<<L, 256>>>(norm2_w, gate_w);
    colsoftmax_kernel<<<2, 1024>>>();
    zero_cnt_kernel<<<1, 32>>>();
    compact_kernel<<<(L+255)/256, 256>>>();
    // 17. routed experts
    gemm_tc<128,128,2,4,0,true><<<grd(L, 2*HID, 128, E), 256, SMEM_BIG>>>(p_x2, e_w1, p_h1,
        L, 2*HID, D, D, D, 2*HID,
        0, (long long)2*HID*D, (long long)L*2*HID, nullptr, nullptr, nullptr, -2);
    silumul_kernel<<<dim3(L, E), 256>>>();
    gemm_tc<128,128,2,4,0,false><<<grd(L, D, 128, E), 256, SMEM_BIG>>>(p_hh, e_w2, p_y,
        L, D, HID, HID, HID, D,
        (long long)L*HID, (long long)D*HID, (long long)L*D, nullptr, nullptr, nullptr, -2);
    gemm_tc<128,128,2,4,5,false><<<grd(L, D, 128, E), 256, SMEM_BIG>>>(p_y, e_lw, p_y,
        L, D, D, D, D, D,
        (long long)L*D, (long long)D*D, 0, e_lb, nullptr, nullptr, -2);
    // 18. final
    final_kernel<<<L, 256>>>(out);
}